// round 7
// baseline (speedup 1.0000x reference)
#include <cuda_runtime.h>
#include <math.h>

#define LTOK 65536          // H*W tokens
#define CDIM 192
#define NHEADS 6
#define HDIM 32
#define HIDD 768

typedef unsigned long long ull;

// -------- scratch (static device globals; no allocation) --------
__device__ float g_xw[LTOK * CDIM];       // LN1'd, shifted, window-partitioned; reused as y0 after QKV
__device__ float g_q[LTOK * CDIM];        // [win,head,n,d]
__device__ float g_k[LTOK * CDIM];
__device__ float g_v[LTOK * CDIM];
__device__ float g_ao[LTOK * CDIM];       // attention out, window order, col = head*32+d
__device__ float g_xr[LTOK * CDIM];       // first residual, token order
__device__ float g_h[LTOK * HIDD];        // MLP hidden
__device__ float g_bias6[NHEADS * 256 * 256];

// -------- packed f32x2 helpers --------
__device__ __forceinline__ ull pk2(float lo, float hi) {
    ull r; asm("mov.b64 %0, {%1,%2};" : "=l"(r) : "f"(lo), "f"(hi)); return r;
}
__device__ __forceinline__ float2 upk(ull v) {
    float2 f; asm("mov.b64 {%0,%1}, %2;" : "=f"(f.x), "=f"(f.y) : "l"(v)); return f;
}
#define FMA2(d, a, b, c) asm("fma.rn.f32x2 %0, %1, %2, %3;" : "=l"(d) : "l"(a), "l"(b), "l"(c))
#define MUL2(d, a, b)    asm("mul.rn.f32x2 %0, %1, %2;" : "=l"(d) : "l"(a), "l"(b))

__device__ __forceinline__ float gelu_exact(float x) {
    return 0.5f * x * (1.0f + erff(x * 0.70710678118654752f));
}

// ============ kernel: relative position bias gather ============
// g_bias6[head][n][m] = rpb_table[rpi[n*256+m]*6 + head]
__global__ void bias6_kernel(const int* __restrict__ rpi, const float* __restrict__ rpb) {
    int id = blockIdx.x * 256 + threadIdx.x;       // 6*65536 total
    int head = id >> 16;
    int nm = id & 65535;
    g_bias6[id] = rpb[rpi[nm] * NHEADS + head];
}

// ============ kernel: LayerNorm (+ optional shift/window permute) ============
// mode==1: read xin (token s), write LN to g_xw at window-permuted row (roll -8,-8 then partition)
// mode==0: read g_xr (token s), write LN to g_xw at same row (y0 for MLP)
__global__ __launch_bounds__(192) void ln_kernel(const float* __restrict__ xin,
                                                 const float* __restrict__ gw,
                                                 const float* __restrict__ bw, int mode) {
    int s = blockIdx.x, c = threadIdx.x;
    const float* in = mode ? xin : g_xr;
    float v = in[s * CDIM + c];

    __shared__ float r1[6], r2[6];
    float t = v;
#pragma unroll
    for (int o = 16; o; o >>= 1) t += __shfl_xor_sync(0xffffffffu, t, o);
    if ((c & 31) == 0) r1[c >> 5] = t;
    __syncthreads();
    float mean = (r1[0] + r1[1] + r1[2] + r1[3] + r1[4] + r1[5]) * (1.0f / CDIM);
    float d = v - mean;
    float t2 = d * d;
#pragma unroll
    for (int o = 16; o; o >>= 1) t2 += __shfl_xor_sync(0xffffffffu, t2, o);
    if ((c & 31) == 0) r2[c >> 5] = t2;
    __syncthreads();
    float var = (r2[0] + r2[1] + r2[2] + r2[3] + r2[4] + r2[5]) * (1.0f / CDIM);
    float o = d * rsqrtf(var + 1e-5f) * gw[c] + bw[c];

    int r;
    if (mode) {
        int h = s >> 8, w = s & 255;
        int i = (h + 248) & 255, j = (w + 248) & 255;     // roll(-8,-8): dst (i,j) holds src (i+8,j+8)
        r = (((i >> 4) << 4) + (j >> 4)) * 256 + ((i & 15) << 4) + (j & 15);
    } else {
        r = s;
    }
    g_xw[r * CDIM + c] = o;
}

// ============ tiled f32x2 SGEMM: BM=128, BN=64, BK=8, 256 threads, 8x4 per thread ============
// MODE 0: A=g_xw, scatter epilogue to g_q/g_k/g_v (q scaled)
// MODE 1: A=g_ao, epilogue: window-reverse + unshift + x residual -> g_xr
// MODE 2: A=g_xw(y0), epilogue: GELU -> g_h
// MODE 3: A=g_h, epilogue: + g_xr residual -> outp (d_out)
template <int MODE>
__device__ __forceinline__ void epi_store(float4 v, int r, int o, float4 b4,
                                          const float* __restrict__ aux,
                                          float* __restrict__ outp) {
    v.x += b4.x; v.y += b4.y; v.z += b4.z; v.w += b4.w;
    if (MODE == 0) {
        int wnd = r >> 8, n = r & 255;
        int which = o / 192;
        int rem = o - which * 192;
        int head = rem >> 5, d = rem & 31;
        float* dst = (which == 0) ? g_q : (which == 1) ? g_k : g_v;
        if (which == 0) {
            const float S = 0.17677669529663687f;  // HD^-0.5
            v.x *= S; v.y *= S; v.z *= S; v.w *= S;
        }
        *(float4*)&dst[((wnd * 6 + head) * 256 + n) * 32 + d] = v;
    } else if (MODE == 1) {
        int wnd = r >> 8, n = r & 255;
        int i = ((wnd >> 4) << 4) + (n >> 4);
        int j = ((wnd & 15) << 4) + (n & 15);
        int h = (i + 8) & 255, w = (j + 8) & 255;          // unshift roll(+8,+8)
        int s = h * 256 + w;
        float4 xa = *(const float4*)&aux[s * CDIM + o];
        v.x += xa.x; v.y += xa.y; v.z += xa.z; v.w += xa.w;
        *(float4*)&g_xr[s * CDIM + o] = v;
    } else if (MODE == 2) {
        v.x = gelu_exact(v.x); v.y = gelu_exact(v.y);
        v.z = gelu_exact(v.z); v.w = gelu_exact(v.w);
        *(float4*)&g_h[r * HIDD + o] = v;
    } else {
        float4 xr4 = *(const float4*)&g_xr[r * CDIM + o];
        v.x += xr4.x; v.y += xr4.y; v.z += xr4.z; v.w += xr4.w;
        *(float4*)&outp[r * CDIM + o] = v;
    }
}

template <int MODE>
__global__ __launch_bounds__(256) void gemm_kernel(const float* __restrict__ Bw,
                                                   const float* __restrict__ bias,
                                                   const float* __restrict__ aux,
                                                   float* __restrict__ outp,
                                                   int K, int N) {
    const float* A = (MODE == 0) ? g_xw : (MODE == 1) ? g_ao : (MODE == 2) ? g_xw : g_h;

    __shared__ __align__(16) float As[8 * 132];   // [k][m] transposed, pad 4
    __shared__ __align__(16) float Bs[8 * 68];    // [k][n], pad 4

    int tid = threadIdx.x;
    int m0 = blockIdx.y * 128, n0 = blockIdx.x * 64;
    int tx = tid & 15, ty = tid >> 4;
    int aRow = tid >> 1, aK = (tid & 1) * 4;
    int bK = tid >> 4, bN = (tid & 15) * 4;

    ull acc[4][4];
#pragma unroll
    for (int i = 0; i < 4; i++)
#pragma unroll
        for (int j = 0; j < 4; j++) acc[i][j] = 0ull;

    for (int kt = 0; kt < K; kt += 8) {
        float4 av = *(const float4*)&A[(m0 + aRow) * K + kt + aK];
        As[(aK + 0) * 132 + aRow] = av.x;
        As[(aK + 1) * 132 + aRow] = av.y;
        As[(aK + 2) * 132 + aRow] = av.z;
        As[(aK + 3) * 132 + aRow] = av.w;
        if (tid < 128) {
            float4 bv = *(const float4*)&Bw[(kt + bK) * N + n0 + bN];
            *(float4*)&Bs[bK * 68 + bN] = bv;
        }
        __syncthreads();
#pragma unroll
        for (int k = 0; k < 8; k++) {
            const ulonglong2* ap = (const ulonglong2*)&As[k * 132 + ty * 8];
            ulonglong2 a01 = ap[0], a23 = ap[1];   // 4 m-pairs (8 rows)
            float4 bv = *(const float4*)&Bs[k * 68 + tx * 4];
            ull bd0 = pk2(bv.x, bv.x), bd1 = pk2(bv.y, bv.y);
            ull bd2 = pk2(bv.z, bv.z), bd3 = pk2(bv.w, bv.w);
            FMA2(acc[0][0], a01.x, bd0, acc[0][0]);
            FMA2(acc[0][1], a01.x, bd1, acc[0][1]);
            FMA2(acc[0][2], a01.x, bd2, acc[0][2]);
            FMA2(acc[0][3], a01.x, bd3, acc[0][3]);
            FMA2(acc[1][0], a01.y, bd0, acc[1][0]);
            FMA2(acc[1][1], a01.y, bd1, acc[1][1]);
            FMA2(acc[1][2], a01.y, bd2, acc[1][2]);
            FMA2(acc[1][3], a01.y, bd3, acc[1][3]);
            FMA2(acc[2][0], a23.x, bd0, acc[2][0]);
            FMA2(acc[2][1], a23.x, bd1, acc[2][1]);
            FMA2(acc[2][2], a23.x, bd2, acc[2][2]);
            FMA2(acc[2][3], a23.x, bd3, acc[2][3]);
            FMA2(acc[3][0], a23.y, bd0, acc[3][0]);
            FMA2(acc[3][1], a23.y, bd1, acc[3][1]);
            FMA2(acc[3][2], a23.y, bd2, acc[3][2]);
            FMA2(acc[3][3], a23.y, bd3, acc[3][3]);
        }
        __syncthreads();
    }

    float4 b4 = *(const float4*)&bias[n0 + tx * 4];
    int ocol = n0 + tx * 4;
#pragma unroll
    for (int mp = 0; mp < 4; mp++) {
        float2 c0 = upk(acc[mp][0]), c1 = upk(acc[mp][1]);
        float2 c2 = upk(acc[mp][2]), c3 = upk(acc[mp][3]);
        int rlo = m0 + ty * 8 + mp * 2;
        epi_store<MODE>(make_float4(c0.x, c1.x, c2.x, c3.x), rlo, ocol, b4, aux, outp);
        epi_store<MODE>(make_float4(c0.y, c1.y, c2.y, c3.y), rlo + 1, ocol, b4, aux, outp);
    }
}

// ============ attention: one block per (window, head), flash-style ============
__global__ __launch_bounds__(256) void attn_kernel(const float* __restrict__ mask) {
    extern __shared__ __align__(16) float sm[];
    float* Ks = sm;            // 256*32
    float* Vs = sm + 8192;     // 256*32

    int bid = blockIdx.x;
    int wnd = bid / 6;
    int head = bid - wnd * 6;
    int tid = threadIdx.x;

    const float* Kg = g_k + (size_t)((wnd * 6 + head) * 256) * 32;
    const float* Vg = g_v + (size_t)((wnd * 6 + head) * 256) * 32;
    for (int i = tid; i < 2048; i += 256) {
        ((float4*)Ks)[i] = ((const float4*)Kg)[i];
        ((float4*)Vs)[i] = ((const float4*)Vg)[i];
    }

    ull q2[16];
    {
        const ulonglong2* Qg = (const ulonglong2*)(g_q + (size_t)(((wnd * 6 + head) * 256) + tid) * 32);
#pragma unroll
        for (int p = 0; p < 8; p++) {
            ulonglong2 qq = Qg[p];
            q2[2 * p] = qq.x;
            q2[2 * p + 1] = qq.y;
        }
    }
    __syncthreads();

    const float* brow = g_bias6 + head * 65536 + tid * 256;
    const float* mrow = mask + (size_t)wnd * 65536 + tid * 256;

    ull acc2[16];
#pragma unroll
    for (int p = 0; p < 16; p++) acc2[p] = 0ull;
    float mx = -1e30f, denom = 0.0f;

    for (int t = 0; t < 8; t++) {
        float s[32];
        float tmax = -1e30f;
#pragma unroll
        for (int mm = 0; mm < 32; mm++) {
            int m = t * 32 + mm;
            const ulonglong2* k2 = (const ulonglong2*)(Ks + m * 32);
            ull da = 0ull, db = 0ull;   // two accumulators to break the dep chain
#pragma unroll
            for (int p = 0; p < 8; p++) {
                ulonglong2 kk = k2[p];
                FMA2(da, q2[2 * p], kk.x, da);
                FMA2(db, q2[2 * p + 1], kk.y, db);
            }
            float2 fa = upk(da), fb = upk(db);
            float sc = (fa.x + fa.y) + (fb.x + fb.y) + brow[m] + mrow[m];
            s[mm] = sc;
            tmax = fmaxf(tmax, sc);
        }
        float nm = fmaxf(mx, tmax);
        float scale = __expf(mx - nm);
        denom *= scale;
        ull sc2 = pk2(scale, scale);
#pragma unroll
        for (int p = 0; p < 16; p++) MUL2(acc2[p], acc2[p], sc2);
#pragma unroll
        for (int mm = 0; mm < 32; mm++) {
            int m = t * 32 + mm;
            float p = __expf(s[mm] - nm);
            denom += p;
            ull p2 = pk2(p, p);
            const ulonglong2* v2 = (const ulonglong2*)(Vs + m * 32);
#pragma unroll
            for (int q = 0; q < 8; q++) {
                ulonglong2 vv = v2[q];
                FMA2(acc2[2 * q], p2, vv.x, acc2[2 * q]);
                FMA2(acc2[2 * q + 1], p2, vv.y, acc2[2 * q + 1]);
            }
        }
        mx = nm;
    }

    float inv = 1.0f / denom;
    float* op = g_ao + (size_t)(wnd * 256 + tid) * CDIM + head * 32;
#pragma unroll
    for (int p = 0; p < 8; p++) {
        float2 a = upk(acc2[2 * p]);
        float2 b = upk(acc2[2 * p + 1]);
        *(float4*)&op[p * 4] = make_float4(a.x * inv, a.y * inv, b.x * inv, b.y * inv);
    }
}

// ============ host launcher ============
extern "C" void kernel_launch(void* const* d_in, const int* in_sizes, int n_in,
                              void* d_out, int out_size) {
    const float* x     = (const float*)d_in[0];
    const int*   rpi   = (const int*)d_in[1];
    const float* mask  = (const float*)d_in[2];
    const float* n1g   = (const float*)d_in[3];
    const float* n1b   = (const float*)d_in[4];
    const float* qkvw  = (const float*)d_in[5];
    const float* qkvb  = (const float*)d_in[6];
    const float* rpb   = (const float*)d_in[7];
    const float* projw = (const float*)d_in[8];
    const float* projb = (const float*)d_in[9];
    const float* n2g   = (const float*)d_in[10];
    const float* n2b   = (const float*)d_in[11];
    const float* fc1w  = (const float*)d_in[12];
    const float* fc1b  = (const float*)d_in[13];
    const float* fc2w  = (const float*)d_in[14];
    const float* fc2b  = (const float*)d_in[15];
    float* out = (float*)d_out;

    cudaFuncSetAttribute(attn_kernel, cudaFuncAttributeMaxDynamicSharedMemorySize, 65536);

    bias6_kernel<<<1536, 256>>>(rpi, rpb);
    ln_kernel<<<65536, 192>>>(x, n1g, n1b, 1);                               // LN1 + shift + partition
    gemm_kernel<0><<<dim3(9, 512), 256>>>(qkvw, qkvb, nullptr, nullptr, 192, 576);   // QKV
    attn_kernel<<<1536, 256, 65536>>>(mask);                                 // windowed attention
    gemm_kernel<1><<<dim3(3, 512), 256>>>(projw, projb, x, nullptr, 192, 192);       // proj + reverse + resid
    ln_kernel<<<65536, 192>>>(x, n2g, n2b, 0);                               // LN2 (reads g_xr)
    gemm_kernel<2><<<dim3(12, 512), 256>>>(fc1w, fc1b, nullptr, nullptr, 192, 768);  // fc1 + GELU
    gemm_kernel<3><<<dim3(3, 512), 256>>>(fc2w, fc2b, nullptr, out, 768, 192);       // fc2 + resid -> out
}

// round 10
// speedup vs baseline: 1.6269x; 1.6269x over previous
#include <cuda_runtime.h>
#include <cuda_bf16.h>
#include <math.h>
#include <stdint.h>

#define LTOK 65536
#define CDIM 192
#define HIDD 768

typedef unsigned long long ull;
typedef unsigned int u32;

// ---------------- scratch (static device globals; no allocation) ----------------
__device__ __nv_bfloat16 g_xwb[LTOK * CDIM];   // LN1 out (window order) / LN2 out (token order)
__device__ float g_q[LTOK * CDIM];             // [win,head,n,d] fp32 (q pre-scaled)
__device__ float g_k[LTOK * CDIM];
__device__ float g_v[LTOK * CDIM];
__device__ __nv_bfloat16 g_aob[LTOK * CDIM];   // attention out, window order, bf16
__device__ float g_xr[LTOK * CDIM];            // first residual, token order, fp32
__device__ __nv_bfloat16 g_hb[LTOK * HIDD];    // MLP hidden, bf16
__device__ float g_bias6[6 * 256 * 256];
// transposed bf16 weights: [N, K] row-major
__device__ __nv_bfloat16 g_wqkv[576 * 192];
__device__ __nv_bfloat16 g_wproj[192 * 192];
__device__ __nv_bfloat16 g_wfc1[768 * 192];
__device__ __nv_bfloat16 g_wfc2[192 * 768];

// ---------------- packed f32x2 helpers (attention) ----------------
__device__ __forceinline__ ull pk2(float lo, float hi) {
    ull r; asm("mov.b64 %0, {%1,%2};" : "=l"(r) : "f"(lo), "f"(hi)); return r;
}
__device__ __forceinline__ float2 upk(ull v) {
    float2 f; asm("mov.b64 {%0,%1}, %2;" : "=f"(f.x), "=f"(f.y) : "l"(v)); return f;
}
#define FMA2(d, a, b, c) asm("fma.rn.f32x2 %0, %1, %2, %3;" : "=l"(d) : "l"(a), "l"(b), "l"(c))

// ---------------- mma.sync helpers ----------------
__device__ __forceinline__ u32 smem_u32(const void* p) {
    u32 a;
    asm("{ .reg .u64 t; cvta.to.shared.u64 t, %1; cvt.u32.u64 %0, t; }" : "=r"(a) : "l"(p));
    return a;
}
#define LDM4(R, addr)                                                           \
    asm volatile("ldmatrix.sync.aligned.m8n8.x4.shared.b16 {%0,%1,%2,%3}, [%4];" \
        : "=r"((R)[0]), "=r"((R)[1]), "=r"((R)[2]), "=r"((R)[3]) : "r"(addr))

#define MMA(dd, A, B0, B1)                                                      \
    asm volatile("mma.sync.aligned.m16n8k16.row.col.f32.bf16.bf16.f32 "          \
        "{%0,%1,%2,%3}, {%4,%5,%6,%7}, {%8,%9}, {%0,%1,%2,%3};"                  \
        : "+f"((dd)[0]), "+f"((dd)[1]), "+f"((dd)[2]), "+f"((dd)[3])             \
        : "r"((A)[0]), "r"((A)[1]), "r"((A)[2]), "r"((A)[3]), "r"(B0), "r"(B1))

__device__ __forceinline__ float gelu_exact(float x) {
    return 0.5f * x * (1.0f + erff(x * 0.70710678118654752f));
}

// ============ weight transpose + bf16 convert: Wt[n*K+k] = W[k*N+n] ============
template <int WID>
__global__ void transw_kernel(const float* __restrict__ W, int K, int N) {
    __nv_bfloat16* Wt = (WID == 0) ? g_wqkv : (WID == 1) ? g_wproj : (WID == 2) ? g_wfc1 : g_wfc2;
    int i = blockIdx.x * 256 + threadIdx.x;
    if (i >= K * N) return;
    int n = i / K, k = i - n * K;
    Wt[i] = __float2bfloat16_rn(W[k * N + n]);
}

// ============ relative position bias gather ============
__global__ void bias6_kernel(const int* __restrict__ rpi, const float* __restrict__ rpb) {
    int id = blockIdx.x * 256 + threadIdx.x;
    int head = id >> 16;
    int nm = id & 65535;
    g_bias6[id] = rpb[rpi[nm] * 6 + head];
}

// ============ LayerNorm (+ optional shift/window permute), bf16 out ============
__global__ __launch_bounds__(192) void ln_kernel(const float* __restrict__ xin,
                                                 const float* __restrict__ gw,
                                                 const float* __restrict__ bw, int mode) {
    int s = blockIdx.x, c = threadIdx.x;
    const float* in = mode ? xin : g_xr;
    float v = in[s * CDIM + c];

    __shared__ float r1[6], r2[6];
    float t = v;
#pragma unroll
    for (int o = 16; o; o >>= 1) t += __shfl_xor_sync(0xffffffffu, t, o);
    if ((c & 31) == 0) r1[c >> 5] = t;
    __syncthreads();
    float mean = (r1[0] + r1[1] + r1[2] + r1[3] + r1[4] + r1[5]) * (1.0f / CDIM);
    float d = v - mean;
    float t2 = d * d;
#pragma unroll
    for (int o = 16; o; o >>= 1) t2 += __shfl_xor_sync(0xffffffffu, t2, o);
    if ((c & 31) == 0) r2[c >> 5] = t2;
    __syncthreads();
    float var = (r2[0] + r2[1] + r2[2] + r2[3] + r2[4] + r2[5]) * (1.0f / CDIM);
    float o = d * rsqrtf(var + 1e-5f) * gw[c] + bw[c];

    int r;
    if (mode) {
        int h = s >> 8, w = s & 255;
        int i = (h + 248) & 255, j = (w + 248) & 255;
        r = (((i >> 4) << 4) + (j >> 4)) * 256 + ((i & 15) << 4) + (j & 15);
    } else {
        r = s;
    }
    g_xwb[r * CDIM + c] = __float2bfloat16_rn(o);
}

// ============ epilogue pair-store ============
template <int MODE>
__device__ __forceinline__ void store2(int r, int n, float2 v,
                                       const float* __restrict__ aux,
                                       float* __restrict__ outp) {
    if (MODE == 0) {
        int which = n / 192;
        int rem = n - which * 192;
        int head = rem >> 5, dd = rem & 31;
        int wnd = r >> 8, nn = r & 255;
        float* dst = ((which == 0) ? g_q : (which == 1) ? g_k : g_v)
                     + (size_t)((wnd * 6 + head) * 256 + nn) * 32 + dd;
        if (which == 0) {
            v.x *= 0.17677669529663687f;
            v.y *= 0.17677669529663687f;
        }
        *(float2*)dst = v;
    } else if (MODE == 1) {
        int wnd = r >> 8, nn = r & 255;
        int i_ = ((wnd >> 4) << 4) + (nn >> 4);
        int j_ = ((wnd & 15) << 4) + (nn & 15);
        int s = (((i_ + 8) & 255) << 8) + ((j_ + 8) & 255);
        float2 a = *(const float2*)(aux + (size_t)s * CDIM + n);
        v.x += a.x; v.y += a.y;
        *(float2*)(g_xr + (size_t)s * CDIM + n) = v;
    } else if (MODE == 2) {
        __nv_bfloat162 h = __floats2bfloat162_rn(gelu_exact(v.x), gelu_exact(v.y));
        *(u32*)(g_hb + (size_t)r * HIDD + n) = *(u32*)&h;
    } else {
        float2 a = *(const float2*)(g_xr + (size_t)r * CDIM + n);
        v.x += a.x; v.y += a.y;
        *(float2*)(outp + (size_t)r * CDIM + n) = v;
    }
}

// ============ mma.sync bf16 GEMM: BM=128, BN=64, BK=32, 256 threads (8 warps 4x2) ============
// MODE 0: A=g_xwb, W=g_wqkv  -> scatter q/k/v fp32 (q scaled)        grid (9, 512)
// MODE 1: A=g_aob, W=g_wproj -> window reverse + x residual -> g_xr  grid (3, 512)
// MODE 2: A=g_xwb, W=g_wfc1  -> GELU -> g_hb bf16                    grid (12, 512)
// MODE 3: A=g_hb,  W=g_wfc2  -> + g_xr -> outp                       grid (3, 512)
template <int MODE>
__global__ __launch_bounds__(256) void tmma(const float* __restrict__ bias,
                                            const float* __restrict__ aux,
                                            float* __restrict__ outp, int K) {
    // 80B row stride: 64B payload + 16B pad -> conflict-free ldmatrix (20-bank row shift)
    __shared__ __align__(16) char As[128 * 80];
    __shared__ __align__(16) char Bs[64 * 80];

    const __nv_bfloat16* Ag = (MODE == 3) ? g_hb : (MODE == 1 ? g_aob : g_xwb);
    const __nv_bfloat16* Wt = (MODE == 0) ? g_wqkv : (MODE == 1) ? g_wproj
                              : (MODE == 2) ? g_wfc1 : g_wfc2;

    int tid = threadIdx.x;
    int w = tid >> 5, l = tid & 31;
    int wm = w & 3, wn = w >> 2;
    int m0 = blockIdx.y * 128, n0 = blockIdx.x * 64;

    int arow = tid >> 2, ach = tid & 3;
    const __nv_bfloat16* Ap  = Ag + (size_t)(m0 + arow) * K + ach * 8;
    const __nv_bfloat16* Ap2 = Ap + (size_t)64 * K;
    const __nv_bfloat16* Bp  = Wt + (size_t)(n0 + arow) * K + ach * 8;

    u32 sa = smem_u32(As), sbB = smem_u32(Bs);
    u32 aBase = sa  + (wm * 32 + (l & 7) + ((l >> 3) & 1) * 8) * 80 + (l >> 4) * 16;
    u32 bBase = sbB + (wn * 32 + (l & 7) + ((l >> 3) & 1) * 8) * 80 + (l >> 4) * 16;

    float d[2][4][4];
#pragma unroll
    for (int mt = 0; mt < 2; mt++)
#pragma unroll
        for (int nj = 0; nj < 4; nj++)
#pragma unroll
            for (int q = 0; q < 4; q++) d[mt][nj][q] = 0.0f;

    uint4 pa0 = *(const uint4*)Ap;
    uint4 pa1 = *(const uint4*)Ap2;
    uint4 pb  = *(const uint4*)Bp;

    const int NIT = K >> 5;
    for (int it = 0; it < NIT; ++it) {
        __syncthreads();
        *(uint4*)(As + arow * 80 + ach * 16)        = pa0;
        *(uint4*)(As + (arow + 64) * 80 + ach * 16) = pa1;
        *(uint4*)(Bs + arow * 80 + ach * 16)        = pb;
        __syncthreads();
        if (it + 1 < NIT) {
            Ap += 32; Ap2 += 32; Bp += 32;
            pa0 = *(const uint4*)Ap;
            pa1 = *(const uint4*)Ap2;
            pb  = *(const uint4*)Bp;
        }
#pragma unroll
        for (int ks = 0; ks < 2; ks++) {
            u32 a0[4], a1[4], r0[4], r1[4];
            LDM4(a0, aBase + ks * 32);
            LDM4(a1, aBase + 1280 + ks * 32);
            LDM4(r0, bBase + ks * 32);
            LDM4(r1, bBase + 1280 + ks * 32);
            MMA(d[0][0], a0, r0[0], r0[2]);
            MMA(d[0][1], a0, r0[1], r0[3]);
            MMA(d[0][2], a0, r1[0], r1[2]);
            MMA(d[0][3], a0, r1[1], r1[3]);
            MMA(d[1][0], a1, r0[0], r0[2]);
            MMA(d[1][1], a1, r0[1], r0[3]);
            MMA(d[1][2], a1, r1[0], r1[2]);
            MMA(d[1][3], a1, r1[1], r1[3]);
        }
    }

    int lq = l >> 2, lr = l & 3;
#pragma unroll
    for (int mt = 0; mt < 2; mt++) {
        int ra = m0 + wm * 32 + mt * 16 + lq;
        int rb = ra + 8;
#pragma unroll
        for (int nj = 0; nj < 4; nj++) {
            int ng = n0 + wn * 32 + nj * 8 + lr * 2;
            float2 b2 = *(const float2*)(bias + ng);
            float2 v0 = make_float2(d[mt][nj][0] + b2.x, d[mt][nj][1] + b2.y);
            float2 v1 = make_float2(d[mt][nj][2] + b2.x, d[mt][nj][3] + b2.y);
            store2<MODE>(ra, ng, v0, aux, outp);
            store2<MODE>(rb, ng, v1, aux, outp);
        }
    }
}

// ============ attention: 2 queries/thread, no online-softmax (scores bounded) ============
__global__ __launch_bounds__(128) void attn2_kernel(const float* __restrict__ mask) {
    extern __shared__ __align__(16) float smf[];
    float* Ks = smf;           // 256*32
    float* Vs = smf + 8192;    // 256*32

    int bid = blockIdx.x;
    int wnd = bid / 6;
    int head = bid - wnd * 6;
    int tid = threadIdx.x;

    const float4* Kg = (const float4*)(g_k + (size_t)((wnd * 6 + head) * 256) * 32);
    const float4* Vg = (const float4*)(g_v + (size_t)((wnd * 6 + head) * 256) * 32);
    for (int i = tid; i < 2048; i += 128) {
        ((float4*)Ks)[i] = Kg[i];
        ((float4*)Vs)[i] = Vg[i];
    }
    int ra = tid, rb = tid + 128;
    ull qa[16], qb[16];
    {
        const ulonglong2* Qa = (const ulonglong2*)(g_q + (size_t)((wnd * 6 + head) * 256 + ra) * 32);
        const ulonglong2* Qb = (const ulonglong2*)(g_q + (size_t)((wnd * 6 + head) * 256 + rb) * 32);
#pragma unroll
        for (int p = 0; p < 8; p++) {
            ulonglong2 x = Qa[p]; qa[2 * p] = x.x; qa[2 * p + 1] = x.y;
            ulonglong2 y = Qb[p]; qb[2 * p] = y.x; qb[2 * p + 1] = y.y;
        }
    }
    __syncthreads();

    const float* browA = g_bias6 + head * 65536 + ra * 256;
    const float* mrowA = mask + (size_t)wnd * 65536 + ra * 256;
    const float* browB = browA + 128 * 256;
    const float* mrowB = mrowA + 128 * 256;

    ull aca[16], acb[16];
#pragma unroll
    for (int p = 0; p < 16; p++) { aca[p] = 0ull; acb[p] = 0ull; }
    float dA = 0.0f, dB = 0.0f;

    for (int m4 = 0; m4 < 64; m4++) {
        float4 bA4 = *(const float4*)(browA + m4 * 4);
        float4 mA4 = *(const float4*)(mrowA + m4 * 4);
        float4 bB4 = *(const float4*)(browB + m4 * 4);
        float4 mB4 = *(const float4*)(mrowB + m4 * 4);
        float addA[4] = {bA4.x + mA4.x, bA4.y + mA4.y, bA4.z + mA4.z, bA4.w + mA4.w};
        float addB[4] = {bB4.x + mB4.x, bB4.y + mB4.y, bB4.z + mB4.z, bB4.w + mB4.w};
#pragma unroll
        for (int j = 0; j < 4; j++) {
            int m = m4 * 4 + j;
            const ulonglong2* k2 = (const ulonglong2*)(Ks + m * 32);
            ull xa = 0ull, ya = 0ull, xb = 0ull, yb = 0ull;
#pragma unroll
            for (int p = 0; p < 8; p++) {
                ulonglong2 kk = k2[p];
                FMA2(xa, qa[2 * p],     kk.x, xa);
                FMA2(ya, qa[2 * p + 1], kk.y, ya);
                FMA2(xb, qb[2 * p],     kk.x, xb);
                FMA2(yb, qb[2 * p + 1], kk.y, yb);
            }
            float2 f1 = upk(xa), f2 = upk(ya), f3 = upk(xb), f4 = upk(yb);
            float pa = __expf((f1.x + f1.y) + (f2.x + f2.y) + addA[j]);
            float pb = __expf((f3.x + f3.y) + (f4.x + f4.y) + addB[j]);
            dA += pa; dB += pb;
            ull pa2 = pk2(pa, pa), pb2 = pk2(pb, pb);
            const ulonglong2* v2 = (const ulonglong2*)(Vs + m * 32);
#pragma unroll
            for (int q = 0; q < 8; q++) {
                ulonglong2 vv = v2[q];
                FMA2(aca[2 * q],     pa2, vv.x, aca[2 * q]);
                FMA2(aca[2 * q + 1], pa2, vv.y, aca[2 * q + 1]);
                FMA2(acb[2 * q],     pb2, vv.x, acb[2 * q]);
                FMA2(acb[2 * q + 1], pb2, vv.y, acb[2 * q + 1]);
            }
        }
    }

    float ia = 1.0f / dA, ib = 1.0f / dB;
    u32 oa[16], ob[16];
#pragma unroll
    for (int p = 0; p < 16; p++) {
        float2 fa = upk(aca[p]);
        __nv_bfloat162 ha = __floats2bfloat162_rn(fa.x * ia, fa.y * ia);
        oa[p] = *(u32*)&ha;
        float2 fb = upk(acb[p]);
        __nv_bfloat162 hb = __floats2bfloat162_rn(fb.x * ib, fb.y * ib);
        ob[p] = *(u32*)&hb;
    }
    __nv_bfloat16* Oa = g_aob + (size_t)(wnd * 256 + ra) * CDIM + head * 32;
    __nv_bfloat16* Ob = g_aob + (size_t)(wnd * 256 + rb) * CDIM + head * 32;
#pragma unroll
    for (int q = 0; q < 4; q++) {
        *(uint4*)(Oa + 8 * q) = make_uint4(oa[4 * q], oa[4 * q + 1], oa[4 * q + 2], oa[4 * q + 3]);
        *(uint4*)(Ob + 8 * q) = make_uint4(ob[4 * q], ob[4 * q + 1], ob[4 * q + 2], ob[4 * q + 3]);
    }
}

// ============ host launcher ============
extern "C" void kernel_launch(void* const* d_in, const int* in_sizes, int n_in,
                              void* d_out, int out_size) {
    const float* x     = (const float*)d_in[0];
    const int*   rpi   = (const int*)d_in[1];
    const float* mask  = (const float*)d_in[2];
    const float* n1g   = (const float*)d_in[3];
    const float* n1b   = (const float*)d_in[4];
    const float* qkvw  = (const float*)d_in[5];
    const float* qkvb  = (const float*)d_in[6];
    const float* rpb   = (const float*)d_in[7];
    const float* projw = (const float*)d_in[8];
    const float* projb = (const float*)d_in[9];
    const float* n2g   = (const float*)d_in[10];
    const float* n2b   = (const float*)d_in[11];
    const float* fc1w  = (const float*)d_in[12];
    const float* fc1b  = (const float*)d_in[13];
    const float* fc2w  = (const float*)d_in[14];
    const float* fc2b  = (const float*)d_in[15];
    float* out = (float*)d_out;

    cudaFuncSetAttribute(attn2_kernel, cudaFuncAttributeMaxDynamicSharedMemorySize, 65536);

    transw_kernel<0><<<(576 * 192 + 255) / 256, 256>>>(qkvw, 192, 576);
    transw_kernel<1><<<(192 * 192 + 255) / 256, 256>>>(projw, 192, 192);
    transw_kernel<2><<<(192 * 768 + 255) / 256, 256>>>(fc1w, 192, 768);
    transw_kernel<3><<<(768 * 192 + 255) / 256, 256>>>(fc2w, 768, 192);
    bias6_kernel<<<1536, 256>>>(rpi, rpb);

    ln_kernel<<<65536, 192>>>(x, n1g, n1b, 1);                          // LN1 + shift + partition
    tmma<0><<<dim3(9, 512), 256>>>(qkvb, nullptr, nullptr, 192);        // QKV -> q/k/v
    attn2_kernel<<<1536, 128, 65536>>>(mask);                           // attention -> g_aob
    tmma<1><<<dim3(3, 512), 256>>>(projb, x, nullptr, 192);             // proj + reverse + resid
    ln_kernel<<<65536, 192>>>(x, n2g, n2b, 0);                          // LN2 (reads g_xr)
    tmma<2><<<dim3(12, 512), 256>>>(fc1b, nullptr, nullptr, 192);       // fc1 + GELU -> g_hb
    tmma<3><<<dim3(3, 512), 256>>>(fc2b, nullptr, out, 768);            // fc2 + resid -> out
}

// round 11
// speedup vs baseline: 4.2406x; 2.6065x over previous
#include <cuda_runtime.h>
#include <cuda_bf16.h>
#include <math.h>
#include <stdint.h>

#define LTOK 65536
#define CDIM 192
#define HIDD 768

typedef unsigned long long ull;
typedef unsigned int u32;

// ---------------- scratch (static device globals; no allocation) ----------------
__device__ __nv_bfloat16 g_xwb[LTOK * CDIM];   // LN1 out (window order) / LN2 out (token order)
__device__ __nv_bfloat16 g_q[LTOK * CDIM];     // [win,head,n,d] bf16 (q pre-scaled)
__device__ __nv_bfloat16 g_k[LTOK * CDIM];
__device__ __nv_bfloat16 g_v[LTOK * CDIM];
__device__ __nv_bfloat16 g_aob[LTOK * CDIM];   // attention out, window order, bf16
__device__ float g_xr[LTOK * CDIM];            // first residual, token order, fp32
__device__ __nv_bfloat16 g_hb[LTOK * HIDD];    // MLP hidden, bf16
__device__ float g_bias6[6 * 256 * 256];
// transposed bf16 weights: [N, K] row-major
__device__ __nv_bfloat16 g_wqkv[576 * 192];
__device__ __nv_bfloat16 g_wproj[192 * 192];
__device__ __nv_bfloat16 g_wfc1[768 * 192];
__device__ __nv_bfloat16 g_wfc2[192 * 768];

// ---------------- mma.sync helpers ----------------
__device__ __forceinline__ u32 smem_u32(const void* p) {
    u32 a;
    asm("{ .reg .u64 t; cvta.to.shared.u64 t, %1; cvt.u32.u64 %0, t; }" : "=r"(a) : "l"(p));
    return a;
}
#define LDM4(R, addr)                                                            \
    asm volatile("ldmatrix.sync.aligned.m8n8.x4.shared.b16 {%0,%1,%2,%3}, [%4];" \
        : "=r"((R)[0]), "=r"((R)[1]), "=r"((R)[2]), "=r"((R)[3]) : "r"(addr))

#define LDM4T(R, addr)                                                           \
    asm volatile("ldmatrix.sync.aligned.m8n8.x4.trans.shared.b16 {%0,%1,%2,%3}, [%4];" \
        : "=r"((R)[0]), "=r"((R)[1]), "=r"((R)[2]), "=r"((R)[3]) : "r"(addr))

#define MMA(dd, A, B0, B1)                                                       \
    asm volatile("mma.sync.aligned.m16n8k16.row.col.f32.bf16.bf16.f32 "          \
        "{%0,%1,%2,%3}, {%4,%5,%6,%7}, {%8,%9}, {%0,%1,%2,%3};"                  \
        : "+f"((dd)[0]), "+f"((dd)[1]), "+f"((dd)[2]), "+f"((dd)[3])             \
        : "r"((A)[0]), "r"((A)[1]), "r"((A)[2]), "r"((A)[3]), "r"(B0), "r"(B1))

__device__ __forceinline__ u32 bfpack(float a, float b) {
    __nv_bfloat162 h = __floats2bfloat162_rn(a, b);
    return *(u32*)&h;
}

__device__ __forceinline__ float gelu_exact(float x) {
    return 0.5f * x * (1.0f + erff(x * 0.70710678118654752f));
}

// ============ weight transpose + bf16 convert: Wt[n*K+k] = W[k*N+n] ============
template <int WID>
__global__ void transw_kernel(const float* __restrict__ W, int K, int N) {
    __nv_bfloat16* Wt = (WID == 0) ? g_wqkv : (WID == 1) ? g_wproj : (WID == 2) ? g_wfc1 : g_wfc2;
    int i = blockIdx.x * 256 + threadIdx.x;
    if (i >= K * N) return;
    int n = i / K, k = i - n * K;
    Wt[i] = __float2bfloat16_rn(W[k * N + n]);
}

// ============ relative position bias gather ============
__global__ void bias6_kernel(const int* __restrict__ rpi, const float* __restrict__ rpb) {
    int id = blockIdx.x * 256 + threadIdx.x;
    int head = id >> 16;
    int nm = id & 65535;
    g_bias6[id] = rpb[rpi[nm] * 6 + head];
}

// ============ LayerNorm: warp-per-token, bf16 out ============
// mode==1: read xin, write to window-permuted row (roll -8,-8 then partition)
// mode==0: read g_xr, write identity row (y0 for MLP)
__global__ __launch_bounds__(256) void ln_kernel(const float* __restrict__ xin,
                                                 const float* __restrict__ gw,
                                                 const float* __restrict__ bw, int mode) {
    int gwid = (blockIdx.x * 256 + threadIdx.x) >> 5;
    int l = threadIdx.x & 31;
    int nwarp = (gridDim.x * 256) >> 5;

    float gg[6], bb[6];
#pragma unroll
    for (int j = 0; j < 6; j++) { gg[j] = gw[l + 32 * j]; bb[j] = bw[l + 32 * j]; }

    const float* src = mode ? xin : g_xr;
    for (int s = gwid; s < LTOK; s += nwarp) {
        const float* in = src + (size_t)s * CDIM;
        float v[6], sum = 0.0f, sq = 0.0f;
#pragma unroll
        for (int j = 0; j < 6; j++) {
            v[j] = in[l + 32 * j];
            sum += v[j];
            sq += v[j] * v[j];
        }
#pragma unroll
        for (int o = 16; o; o >>= 1) {
            sum += __shfl_xor_sync(0xffffffffu, sum, o);
            sq  += __shfl_xor_sync(0xffffffffu, sq, o);
        }
        float mean = sum * (1.0f / CDIM);
        float var = sq * (1.0f / CDIM) - mean * mean;
        float rs = rsqrtf(var + 1e-5f);
        int r;
        if (mode) {
            int h = s >> 8, w = s & 255;
            int i = (h + 248) & 255, j = (w + 248) & 255;
            r = (((i >> 4) << 4) + (j >> 4)) * 256 + ((i & 15) << 4) + (j & 15);
        } else {
            r = s;
        }
        __nv_bfloat16* dst = g_xwb + (size_t)r * CDIM;
#pragma unroll
        for (int j = 0; j < 6; j++)
            dst[l + 32 * j] = __float2bfloat16_rn((v[j] - mean) * rs * gg[j] + bb[j]);
    }
}

// ============ epilogue pair-store ============
template <int MODE>
__device__ __forceinline__ void store2(int r, int n, float2 v,
                                       const float* __restrict__ aux,
                                       float* __restrict__ outp) {
    if (MODE == 0) {
        int which = n / 192;
        int rem = n - which * 192;
        int head = rem >> 5, dd = rem & 31;
        int wnd = r >> 8, nn = r & 255;
        __nv_bfloat16* dst = ((which == 0) ? g_q : (which == 1) ? g_k : g_v)
                             + (size_t)((wnd * 6 + head) * 256 + nn) * 32 + dd;
        if (which == 0) {
            v.x *= 0.17677669529663687f;
            v.y *= 0.17677669529663687f;
        }
        *(u32*)dst = bfpack(v.x, v.y);
    } else if (MODE == 1) {
        int wnd = r >> 8, nn = r & 255;
        int i_ = ((wnd >> 4) << 4) + (nn >> 4);
        int j_ = ((wnd & 15) << 4) + (nn & 15);
        int s = (((i_ + 8) & 255) << 8) + ((j_ + 8) & 255);
        float2 a = *(const float2*)(aux + (size_t)s * CDIM + n);
        v.x += a.x; v.y += a.y;
        *(float2*)(g_xr + (size_t)s * CDIM + n) = v;
    } else if (MODE == 2) {
        *(u32*)(g_hb + (size_t)r * HIDD + n) = bfpack(gelu_exact(v.x), gelu_exact(v.y));
    } else {
        float2 a = *(const float2*)(g_xr + (size_t)r * CDIM + n);
        v.x += a.x; v.y += a.y;
        *(float2*)(outp + (size_t)r * CDIM + n) = v;
    }
}

// ============ mma.sync bf16 GEMM: BM=128, BN=64, BK=32, 256 threads (8 warps 4x2) ============
template <int MODE>
__global__ __launch_bounds__(256) void tmma(const float* __restrict__ bias,
                                            const float* __restrict__ aux,
                                            float* __restrict__ outp, int K) {
    __shared__ __align__(16) char As[128 * 80];
    __shared__ __align__(16) char Bs[64 * 80];

    const __nv_bfloat16* Ag = (MODE == 3) ? g_hb : (MODE == 1 ? g_aob : g_xwb);
    const __nv_bfloat16* Wt = (MODE == 0) ? g_wqkv : (MODE == 1) ? g_wproj
                              : (MODE == 2) ? g_wfc1 : g_wfc2;

    int tid = threadIdx.x;
    int w = tid >> 5, l = tid & 31;
    int wm = w & 3, wn = w >> 2;
    int m0 = blockIdx.y * 128, n0 = blockIdx.x * 64;

    int arow = tid >> 2, ach = tid & 3;
    const __nv_bfloat16* Ap  = Ag + (size_t)(m0 + arow) * K + ach * 8;
    const __nv_bfloat16* Ap2 = Ap + (size_t)64 * K;
    const __nv_bfloat16* Bp  = Wt + (size_t)(n0 + arow) * K + ach * 8;

    u32 sa = smem_u32(As), sbB = smem_u32(Bs);
    u32 aBase = sa  + (wm * 32 + (l & 7) + ((l >> 3) & 1) * 8) * 80 + (l >> 4) * 16;
    u32 bBase = sbB + (wn * 32 + (l & 7) + ((l >> 3) & 1) * 8) * 80 + (l >> 4) * 16;

    float d[2][4][4];
#pragma unroll
    for (int mt = 0; mt < 2; mt++)
#pragma unroll
        for (int nj = 0; nj < 4; nj++)
#pragma unroll
            for (int q = 0; q < 4; q++) d[mt][nj][q] = 0.0f;

    uint4 pa0 = *(const uint4*)Ap;
    uint4 pa1 = *(const uint4*)Ap2;
    uint4 pb  = *(const uint4*)Bp;

    const int NIT = K >> 5;
    for (int it = 0; it < NIT; ++it) {
        __syncthreads();
        *(uint4*)(As + arow * 80 + ach * 16)        = pa0;
        *(uint4*)(As + (arow + 64) * 80 + ach * 16) = pa1;
        *(uint4*)(Bs + arow * 80 + ach * 16)        = pb;
        __syncthreads();
        if (it + 1 < NIT) {
            Ap += 32; Ap2 += 32; Bp += 32;
            pa0 = *(const uint4*)Ap;
            pa1 = *(const uint4*)Ap2;
            pb  = *(const uint4*)Bp;
        }
#pragma unroll
        for (int ks = 0; ks < 2; ks++) {
            u32 a0[4], a1[4], r0[4], r1[4];
            LDM4(a0, aBase + ks * 32);
            LDM4(a1, aBase + 1280 + ks * 32);
            LDM4(r0, bBase + ks * 32);
            LDM4(r1, bBase + 1280 + ks * 32);
            MMA(d[0][0], a0, r0[0], r0[2]);
            MMA(d[0][1], a0, r0[1], r0[3]);
            MMA(d[0][2], a0, r1[0], r1[2]);
            MMA(d[0][3], a0, r1[1], r1[3]);
            MMA(d[1][0], a1, r0[0], r0[2]);
            MMA(d[1][1], a1, r0[1], r0[3]);
            MMA(d[1][2], a1, r1[0], r1[2]);
            MMA(d[1][3], a1, r1[1], r1[3]);
        }
    }

    int lq = l >> 2, lr = l & 3;
#pragma unroll
    for (int mt = 0; mt < 2; mt++) {
        int ra = m0 + wm * 32 + mt * 16 + lq;
        int rb = ra + 8;
#pragma unroll
        for (int nj = 0; nj < 4; nj++) {
            int ng = n0 + wn * 32 + nj * 8 + lr * 2;
            float2 b2 = *(const float2*)(bias + ng);
            float2 v0 = make_float2(d[mt][nj][0] + b2.x, d[mt][nj][1] + b2.y);
            float2 v1 = make_float2(d[mt][nj][2] + b2.x, d[mt][nj][3] + b2.y);
            store2<MODE>(ra, ng, v0, aux, outp);
            store2<MODE>(rb, ng, v1, aux, outp);
        }
    }
}

// ============ tensor-core attention: one block per (window, head) ============
// 8 warps, two 128-query passes; warp owns 16 rows. S=Q*K^T (m16n8k16),
// bias(+mask only for border windows), exp fp32, P packed to a-frags, O=P*V.
#define ATT_SMEM (256 * 80 * 3)
__global__ __launch_bounds__(256) void attn_mma(const float* __restrict__ mask) {
    extern __shared__ __align__(16) char sm[];
    char* Qs = sm;
    char* Ksm = sm + 256 * 80;
    char* Vsm = sm + 2 * 256 * 80;

    int bid = blockIdx.x;
    int wnd = bid / 6;
    int head = bid - wnd * 6;
    int tid = threadIdx.x;

    size_t gbase = (size_t)((wnd * 6 + head) * 256) * 32;
    const uint4* Qg = (const uint4*)(g_q + gbase);
    const uint4* Kg = (const uint4*)(g_k + gbase);
    const uint4* Vg = (const uint4*)(g_v + gbase);
    for (int i = tid; i < 1024; i += 256) {
        int row = i >> 2, c4 = i & 3;
        int off = row * 80 + c4 * 16;
        *(uint4*)(Qs + off)  = Qg[i];
        *(uint4*)(Ksm + off) = Kg[i];
        *(uint4*)(Vsm + off) = Vg[i];
    }
    __syncthreads();

    int w = tid >> 5, l = tid & 31;
    u32 sQ = smem_u32(Qs), sK = smem_u32(Ksm), sV = smem_u32(Vsm);
    bool border = ((wnd >> 4) == 15) || ((wnd & 15) == 15);

#pragma unroll 1
    for (int hh = 0; hh < 2; hh++) {
        int qr = hh * 128 + w * 16;
        u32 qa[8];
        LDM4(qa,     sQ + (qr + (l & 15)) * 80 + (l >> 4) * 16);
        LDM4(qa + 4, sQ + (qr + (l & 15)) * 80 + 32 + (l >> 4) * 16);

        float d[32][4];
#pragma unroll
        for (int t = 0; t < 32; t++)
#pragma unroll
            for (int q = 0; q < 4; q++) d[t][q] = 0.0f;

#pragma unroll
        for (int t = 0; t < 32; t++) {
            u32 kb[4];
            LDM4(kb, sK + (t * 8 + (l & 7)) * 80 + (l >> 3) * 16);
            MMA(d[t], qa, kb[0], kb[1]);
            MMA(d[t], qa + 4, kb[2], kb[3]);
        }

        int r0 = qr + (l >> 2);
        const float* bA = g_bias6 + head * 65536 + r0 * 256;
        const float* bB = bA + 2048;
        const float* mA = mask + (size_t)wnd * 65536 + r0 * 256;
        const float* mB = mA + 2048;

        float sA = 0.0f, sB = 0.0f;
        u32 pbf[16][4];
#pragma unroll
        for (int t = 0; t < 32; t++) {
            int c = t * 8 + 2 * (l & 3);
            float2 aA = *(const float2*)(bA + c);
            float2 aB = *(const float2*)(bB + c);
            if (border) {
                float2 ma = *(const float2*)(mA + c);
                float2 mb = *(const float2*)(mB + c);
                aA.x += ma.x; aA.y += ma.y;
                aB.x += mb.x; aB.y += mb.y;
            }
            float p0 = __expf(d[t][0] + aA.x);
            float p1 = __expf(d[t][1] + aA.y);
            float p2 = __expf(d[t][2] + aB.x);
            float p3 = __expf(d[t][3] + aB.y);
            sA += p0 + p1;
            sB += p2 + p3;
            int kt = t >> 1, s4 = (t & 1) * 2;
            pbf[kt][s4]     = bfpack(p0, p1);
            pbf[kt][s4 + 1] = bfpack(p2, p3);
        }
        sA += __shfl_xor_sync(0xffffffffu, sA, 1);
        sA += __shfl_xor_sync(0xffffffffu, sA, 2);
        sB += __shfl_xor_sync(0xffffffffu, sB, 1);
        sB += __shfl_xor_sync(0xffffffffu, sB, 2);
        float invA = 1.0f / sA, invB = 1.0f / sB;

        float o[4][4];
#pragma unroll
        for (int nt = 0; nt < 4; nt++)
#pragma unroll
            for (int q = 0; q < 4; q++) o[nt][q] = 0.0f;

#pragma unroll
        for (int kt = 0; kt < 16; kt++) {
            u32 v0[4], v1[4];
            u32 vaddr = sV + (kt * 16 + (l & 7) + ((l >> 3) & 1) * 8) * 80 + (l >> 4) * 16;
            LDM4T(v0, vaddr);
            LDM4T(v1, vaddr + 32);
            MMA(o[0], pbf[kt], v0[0], v0[1]);
            MMA(o[1], pbf[kt], v0[2], v0[3]);
            MMA(o[2], pbf[kt], v1[0], v1[1]);
            MMA(o[3], pbf[kt], v1[2], v1[3]);
        }

        __nv_bfloat16* OA = g_aob + (size_t)(wnd * 256 + r0) * CDIM + head * 32;
        __nv_bfloat16* OB = OA + (size_t)8 * CDIM;
#pragma unroll
        for (int nt = 0; nt < 4; nt++) {
            int c = nt * 8 + 2 * (l & 3);
            *(u32*)(OA + c) = bfpack(o[nt][0] * invA, o[nt][1] * invA);
            *(u32*)(OB + c) = bfpack(o[nt][2] * invB, o[nt][3] * invB);
        }
    }
}

// ============ host launcher ============
extern "C" void kernel_launch(void* const* d_in, const int* in_sizes, int n_in,
                              void* d_out, int out_size) {
    const float* x     = (const float*)d_in[0];
    const int*   rpi   = (const int*)d_in[1];
    const float* mask  = (const float*)d_in[2];
    const float* n1g   = (const float*)d_in[3];
    const float* n1b   = (const float*)d_in[4];
    const float* qkvw  = (const float*)d_in[5];
    const float* qkvb  = (const float*)d_in[6];
    const float* rpb   = (const float*)d_in[7];
    const float* projw = (const float*)d_in[8];
    const float* projb = (const float*)d_in[9];
    const float* n2g   = (const float*)d_in[10];
    const float* n2b   = (const float*)d_in[11];
    const float* fc1w  = (const float*)d_in[12];
    const float* fc1b  = (const float*)d_in[13];
    const float* fc2w  = (const float*)d_in[14];
    const float* fc2b  = (const float*)d_in[15];
    float* out = (float*)d_out;

    cudaFuncSetAttribute(attn_mma, cudaFuncAttributeMaxDynamicSharedMemorySize, ATT_SMEM);

    transw_kernel<0><<<(576 * 192 + 255) / 256, 256>>>(qkvw, 192, 576);
    transw_kernel<1><<<(192 * 192 + 255) / 256, 256>>>(projw, 192, 192);
    transw_kernel<2><<<(192 * 768 + 255) / 256, 256>>>(fc1w, 192, 768);
    transw_kernel<3><<<(768 * 192 + 255) / 256, 256>>>(fc2w, 768, 192);
    bias6_kernel<<<1536, 256>>>(rpi, rpb);

    ln_kernel<<<512, 256>>>(x, n1g, n1b, 1);                            // LN1 + shift + partition
    tmma<0><<<dim3(9, 512), 256>>>(qkvb, nullptr, nullptr, 192);        // QKV -> q/k/v bf16
    attn_mma<<<1536, 256, ATT_SMEM>>>(mask);                            // attention -> g_aob
    tmma<1><<<dim3(3, 512), 256>>>(projb, x, nullptr, 192);             // proj + reverse + resid
    ln_kernel<<<512, 256>>>(x, n2g, n2b, 0);                            // LN2 (reads g_xr)
    tmma<2><<<dim3(12, 512), 256>>>(fc1b, nullptr, nullptr, 192);       // fc1 + GELU -> g_hb
    tmma<3><<<dim3(3, 512), 256>>>(fc2b, nullptr, out, 768);            // fc2 + resid -> out
}

// round 12
// speedup vs baseline: 4.2982x; 1.0136x over previous
#include <cuda_runtime.h>
#include <cuda_bf16.h>
#include <math.h>
#include <stdint.h>

#define LTOK 65536
#define CDIM 192
#define HIDD 768

typedef unsigned long long ull;
typedef unsigned int u32;

// ---------------- scratch (static device globals; no allocation) ----------------
__device__ __nv_bfloat16 g_xwb[LTOK * CDIM];   // LN1 out (window order) / LN2 out (token order)
__device__ __nv_bfloat16 g_q[LTOK * CDIM];     // [win,head,n,d] bf16 (q pre-scaled)
__device__ __nv_bfloat16 g_k[LTOK * CDIM];
__device__ __nv_bfloat16 g_v[LTOK * CDIM];
__device__ __nv_bfloat16 g_aob[LTOK * CDIM];   // attention out, window order, bf16
__device__ float g_xr[LTOK * CDIM];            // first residual, token order, fp32
__device__ __nv_bfloat16 g_hb[LTOK * HIDD];    // MLP hidden, bf16
__device__ __nv_bfloat16 g_bias6b[6 * 256 * 256];   // rel-pos bias, bf16
// transposed bf16 weights: [N, K] row-major
__device__ __nv_bfloat16 g_wqkv[576 * 192];
__device__ __nv_bfloat16 g_wproj[192 * 192];
__device__ __nv_bfloat16 g_wfc1[768 * 192];
__device__ __nv_bfloat16 g_wfc2[192 * 768];

// ---------------- mma.sync helpers ----------------
__device__ __forceinline__ u32 smem_u32(const void* p) {
    u32 a;
    asm("{ .reg .u64 t; cvta.to.shared.u64 t, %1; cvt.u32.u64 %0, t; }" : "=r"(a) : "l"(p));
    return a;
}
#define LDM4(R, addr)                                                            \
    asm volatile("ldmatrix.sync.aligned.m8n8.x4.shared.b16 {%0,%1,%2,%3}, [%4];" \
        : "=r"((R)[0]), "=r"((R)[1]), "=r"((R)[2]), "=r"((R)[3]) : "r"(addr))

#define LDM4T(R, addr)                                                           \
    asm volatile("ldmatrix.sync.aligned.m8n8.x4.trans.shared.b16 {%0,%1,%2,%3}, [%4];" \
        : "=r"((R)[0]), "=r"((R)[1]), "=r"((R)[2]), "=r"((R)[3]) : "r"(addr))

#define MMA(dd, A, B0, B1)                                                       \
    asm volatile("mma.sync.aligned.m16n8k16.row.col.f32.bf16.bf16.f32 "          \
        "{%0,%1,%2,%3}, {%4,%5,%6,%7}, {%8,%9}, {%0,%1,%2,%3};"                  \
        : "+f"((dd)[0]), "+f"((dd)[1]), "+f"((dd)[2]), "+f"((dd)[3])             \
        : "r"((A)[0]), "r"((A)[1]), "r"((A)[2]), "r"((A)[3]), "r"(B0), "r"(B1))

__device__ __forceinline__ u32 bfpack(float a, float b) {
    __nv_bfloat162 h = __floats2bfloat162_rn(a, b);
    return *(u32*)&h;
}

__device__ __forceinline__ float gelu_exact(float x) {
    return 0.5f * x * (1.0f + erff(x * 0.70710678118654752f));
}

// ============ all weight transposes fused: Wt[n*K+k] = W[k*N+n] ============
__global__ void transw_all(const float* __restrict__ qkvw, const float* __restrict__ projw,
                           const float* __restrict__ fc1w, const float* __restrict__ fc2w) {
    int i = blockIdx.x * 256 + threadIdx.x;
    const float* W; __nv_bfloat16* Wt; int K, N, j;
    if (i < 110592)      { j = i;          W = qkvw; Wt = g_wqkv;  K = 192; N = 576; }
    else if (i < 147456) { j = i - 110592; W = projw; Wt = g_wproj; K = 192; N = 192; }
    else if (i < 294912) { j = i - 147456; W = fc1w; Wt = g_wfc1;  K = 192; N = 768; }
    else                 { j = i - 294912; W = fc2w; Wt = g_wfc2;  K = 768; N = 192; }
    int n = j / K, k = j - n * K;
    Wt[j] = __float2bfloat16_rn(W[k * N + n]);
}

// ============ relative position bias gather (bf16) ============
__global__ void bias6_kernel(const int* __restrict__ rpi, const float* __restrict__ rpb) {
    int id = blockIdx.x * 256 + threadIdx.x;
    int head = id >> 16;
    int nm = id & 65535;
    g_bias6b[id] = __float2bfloat16_rn(rpb[rpi[nm] * 6 + head]);
}

// ============ LayerNorm: warp-per-token, bf16 out ============
__global__ __launch_bounds__(256) void ln_kernel(const float* __restrict__ xin,
                                                 const float* __restrict__ gw,
                                                 const float* __restrict__ bw, int mode) {
    int gwid = (blockIdx.x * 256 + threadIdx.x) >> 5;
    int l = threadIdx.x & 31;
    int nwarp = (gridDim.x * 256) >> 5;

    float gg[6], bb[6];
#pragma unroll
    for (int j = 0; j < 6; j++) { gg[j] = gw[l + 32 * j]; bb[j] = bw[l + 32 * j]; }

    const float* src = mode ? xin : g_xr;
    for (int s = gwid; s < LTOK; s += nwarp) {
        const float* in = src + (size_t)s * CDIM;
        float v[6], sum = 0.0f, sq = 0.0f;
#pragma unroll
        for (int j = 0; j < 6; j++) {
            v[j] = in[l + 32 * j];
            sum += v[j];
            sq += v[j] * v[j];
        }
#pragma unroll
        for (int o = 16; o; o >>= 1) {
            sum += __shfl_xor_sync(0xffffffffu, sum, o);
            sq  += __shfl_xor_sync(0xffffffffu, sq, o);
        }
        float mean = sum * (1.0f / CDIM);
        float var = sq * (1.0f / CDIM) - mean * mean;
        float rs = rsqrtf(var + 1e-5f);
        int r;
        if (mode) {
            int h = s >> 8, w = s & 255;
            int i = (h + 248) & 255, j = (w + 248) & 255;
            r = (((i >> 4) << 4) + (j >> 4)) * 256 + ((i & 15) << 4) + (j & 15);
        } else {
            r = s;
        }
        __nv_bfloat16* dst = g_xwb + (size_t)r * CDIM;
#pragma unroll
        for (int j = 0; j < 6; j++)
            dst[l + 32 * j] = __float2bfloat16_rn((v[j] - mean) * rs * gg[j] + bb[j]);
    }
}

// ============ epilogue pair-store ============
template <int MODE>
__device__ __forceinline__ void store2(int r, int n, float2 v,
                                       const float* __restrict__ aux,
                                       float* __restrict__ outp) {
    if (MODE == 0) {
        int which = n / 192;
        int rem = n - which * 192;
        int head = rem >> 5, dd = rem & 31;
        int wnd = r >> 8, nn = r & 255;
        __nv_bfloat16* dst = ((which == 0) ? g_q : (which == 1) ? g_k : g_v)
                             + (size_t)((wnd * 6 + head) * 256 + nn) * 32 + dd;
        if (which == 0) {
            v.x *= 0.17677669529663687f;
            v.y *= 0.17677669529663687f;
        }
        *(u32*)dst = bfpack(v.x, v.y);
    } else if (MODE == 1) {
        int wnd = r >> 8, nn = r & 255;
        int i_ = ((wnd >> 4) << 4) + (nn >> 4);
        int j_ = ((wnd & 15) << 4) + (nn & 15);
        int s = (((i_ + 8) & 255) << 8) + ((j_ + 8) & 255);
        float2 a = *(const float2*)(aux + (size_t)s * CDIM + n);
        v.x += a.x; v.y += a.y;
        *(float2*)(g_xr + (size_t)s * CDIM + n) = v;
    } else if (MODE == 2) {
        *(u32*)(g_hb + (size_t)r * HIDD + n) = bfpack(gelu_exact(v.x), gelu_exact(v.y));
    } else {
        float2 a = *(const float2*)(g_xr + (size_t)r * CDIM + n);
        v.x += a.x; v.y += a.y;
        *(float2*)(outp + (size_t)r * CDIM + n) = v;
    }
}

// ============ A-resident GEMM for K=192: BM=128, n-loop inside block ============
// A tile (128x192 bf16, 50KB) loaded once; all 24 a-frags kept in registers.
// Per n-tile (64 cols): stream weight tile with register prefetch, 12 k-steps.
// MODE 0: QKV (NT=9)  MODE 1: proj (NT=3)  MODE 2: fc1 (NT=12)
#define ARES_SMEM (128 * 400 + 64 * 400)
template <int MODE>
__global__ __launch_bounds__(256) void tmmaA(const float* __restrict__ bias,
                                             const float* __restrict__ aux,
                                             float* __restrict__ outp, int NT) {
    extern __shared__ __align__(16) char sm[];
    char* As = sm;               // 128 rows * 400B (384 payload + 16 pad)
    char* Bs = sm + 128 * 400;   // 64 rows * 400B

    const __nv_bfloat16* Ag = (MODE == 1) ? g_aob : g_xwb;
    const __nv_bfloat16* Wt = (MODE == 0) ? g_wqkv : (MODE == 1) ? g_wproj : g_wfc1;

    int tid = threadIdx.x;
    int w = tid >> 5, l = tid & 31;
    int wm = w & 3, wn = w >> 2;
    int m0 = blockIdx.x * 128;

    // prefetch B tile 0 into registers
    uint4 pf[6];
#pragma unroll
    for (int j = 0; j < 6; j++) {
        int id = tid + j * 256;
        int row = id / 24, ch = id - row * 24;
        pf[j] = *(const uint4*)(Wt + (size_t)row * 192 + ch * 8);
    }

    // load A tile
#pragma unroll
    for (int j = 0; j < 12; j++) {
        int id = tid + j * 256;
        int row = id / 24, ch = id - row * 24;
        *(uint4*)(As + row * 400 + ch * 16) =
            *(const uint4*)(Ag + (size_t)(m0 + row) * 192 + ch * 8);
    }
    __syncthreads();

    // all a-fragments in registers: [mt][ks][4]
    u32 sa = smem_u32(As), sbB = smem_u32(Bs);
    u32 areg[2][12][4];
#pragma unroll
    for (int mt = 0; mt < 2; mt++) {
        u32 base = sa + (wm * 32 + mt * 16 + (l & 15)) * 400 + (l >> 4) * 16;
#pragma unroll
        for (int ks = 0; ks < 12; ks++) LDM4(areg[mt][ks], base + ks * 32);
    }

    u32 bBase = sbB + (wn * 32 + (l & 7) + ((l >> 3) & 1) * 8) * 400 + (l >> 4) * 16;
    int lq = l >> 2, lr = l & 3;

    for (int nt = 0; nt < NT; nt++) {
        __syncthreads();
#pragma unroll
        for (int j = 0; j < 6; j++) {
            int id = tid + j * 256;
            int row = id / 24, ch = id - row * 24;
            *(uint4*)(Bs + row * 400 + ch * 16) = pf[j];
        }
        __syncthreads();
        if (nt + 1 < NT) {
            const __nv_bfloat16* Wn = Wt + (size_t)(nt + 1) * 64 * 192;
#pragma unroll
            for (int j = 0; j < 6; j++) {
                int id = tid + j * 256;
                int row = id / 24, ch = id - row * 24;
                pf[j] = *(const uint4*)(Wn + (size_t)row * 192 + ch * 8);
            }
        }

        float d[2][4][4];
#pragma unroll
        for (int mt = 0; mt < 2; mt++)
#pragma unroll
            for (int nj = 0; nj < 4; nj++)
#pragma unroll
                for (int q = 0; q < 4; q++) d[mt][nj][q] = 0.0f;

#pragma unroll
        for (int ks = 0; ks < 12; ks++) {
            u32 r0[4], r1[4];
            LDM4(r0, bBase + ks * 32);
            LDM4(r1, bBase + 6400 + ks * 32);
            MMA(d[0][0], areg[0][ks], r0[0], r0[2]);
            MMA(d[0][1], areg[0][ks], r0[1], r0[3]);
            MMA(d[0][2], areg[0][ks], r1[0], r1[2]);
            MMA(d[0][3], areg[0][ks], r1[1], r1[3]);
            MMA(d[1][0], areg[1][ks], r0[0], r0[2]);
            MMA(d[1][1], areg[1][ks], r0[1], r0[3]);
            MMA(d[1][2], areg[1][ks], r1[0], r1[2]);
            MMA(d[1][3], areg[1][ks], r1[1], r1[3]);
        }

#pragma unroll
        for (int mt = 0; mt < 2; mt++) {
            int ra = m0 + wm * 32 + mt * 16 + lq;
            int rb = ra + 8;
#pragma unroll
            for (int nj = 0; nj < 4; nj++) {
                int ng = nt * 64 + wn * 32 + nj * 8 + lr * 2;
                float2 b2 = *(const float2*)(bias + ng);
                float2 v0 = make_float2(d[mt][nj][0] + b2.x, d[mt][nj][1] + b2.y);
                float2 v1 = make_float2(d[mt][nj][2] + b2.x, d[mt][nj][3] + b2.y);
                store2<MODE>(ra, ng, v0, aux, outp);
                store2<MODE>(rb, ng, v1, aux, outp);
            }
        }
    }
}

// ============ fc2 GEMM: K=768, BM=128, BN=192 single pass (A read once) ============
__global__ __launch_bounds__(256) void tmmaF(const float* __restrict__ bias,
                                             float* __restrict__ outp) {
    __shared__ __align__(16) char As[128 * 80];
    __shared__ __align__(16) char Bs[192 * 80];

    int tid = threadIdx.x;
    int w = tid >> 5, l = tid & 31;
    int wm = w & 3, wn = w >> 2;   // 4 x 2 warps; warp tile 32 x 96
    int m0 = blockIdx.x * 128;

    const __nv_bfloat16* Ag = g_hb;
    const __nv_bfloat16* Wt = g_wfc2;

    u32 sa = smem_u32(As), sbB = smem_u32(Bs);
    u32 aBase = sa  + (wm * 32 + (l & 7) + ((l >> 3) & 1) * 8) * 80 + (l >> 4) * 16;
    u32 bBase = sbB + (wn * 96 + (l & 7) + ((l >> 3) & 1) * 8) * 80 + (l >> 4) * 16;

    float d[2][12][4];
#pragma unroll
    for (int mt = 0; mt < 2; mt++)
#pragma unroll
        for (int nj = 0; nj < 12; nj++)
#pragma unroll
            for (int q = 0; q < 4; q++) d[mt][nj][q] = 0.0f;

    uint4 pa[2], pb[3];
#pragma unroll
    for (int j = 0; j < 2; j++) {
        int id = tid + j * 256;
        pa[j] = *(const uint4*)(Ag + (size_t)(m0 + (id >> 2)) * HIDD + (id & 3) * 8);
    }
#pragma unroll
    for (int j = 0; j < 3; j++) {
        int id = tid + j * 256;
        pb[j] = *(const uint4*)(Wt + (size_t)(id >> 2) * HIDD + (id & 3) * 8);
    }

    for (int kt = 0; kt < 24; kt++) {
        __syncthreads();
#pragma unroll
        for (int j = 0; j < 2; j++) {
            int id = tid + j * 256;
            *(uint4*)(As + (id >> 2) * 80 + (id & 3) * 16) = pa[j];
        }
#pragma unroll
        for (int j = 0; j < 3; j++) {
            int id = tid + j * 256;
            *(uint4*)(Bs + (id >> 2) * 80 + (id & 3) * 16) = pb[j];
        }
        __syncthreads();
        if (kt + 1 < 24) {
            int kc = (kt + 1) * 32;
#pragma unroll
            for (int j = 0; j < 2; j++) {
                int id = tid + j * 256;
                pa[j] = *(const uint4*)(Ag + (size_t)(m0 + (id >> 2)) * HIDD + kc + (id & 3) * 8);
            }
#pragma unroll
            for (int j = 0; j < 3; j++) {
                int id = tid + j * 256;
                pb[j] = *(const uint4*)(Wt + (size_t)(id >> 2) * HIDD + kc + (id & 3) * 8);
            }
        }
#pragma unroll
        for (int ks = 0; ks < 2; ks++) {
            u32 a0[4], a1[4];
            LDM4(a0, aBase + ks * 32);
            LDM4(a1, aBase + 1280 + ks * 32);
#pragma unroll
            for (int g = 0; g < 6; g++) {
                u32 rg[4];
                LDM4(rg, bBase + g * 1280 + ks * 32);
                MMA(d[0][2 * g],     a0, rg[0], rg[2]);
                MMA(d[0][2 * g + 1], a0, rg[1], rg[3]);
                MMA(d[1][2 * g],     a1, rg[0], rg[2]);
                MMA(d[1][2 * g + 1], a1, rg[1], rg[3]);
            }
        }
    }

    int lq = l >> 2, lr = l & 3;
#pragma unroll
    for (int mt = 0; mt < 2; mt++) {
        int ra = m0 + wm * 32 + mt * 16 + lq;
        int rb = ra + 8;
#pragma unroll
        for (int nj = 0; nj < 12; nj++) {
            int ng = wn * 96 + nj * 8 + lr * 2;
            float2 b2 = *(const float2*)(bias + ng);
            float2 v0 = make_float2(d[mt][nj][0] + b2.x, d[mt][nj][1] + b2.y);
            float2 v1 = make_float2(d[mt][nj][2] + b2.x, d[mt][nj][3] + b2.y);
            store2<3>(ra, ng, v0, nullptr, outp);
            store2<3>(rb, ng, v1, nullptr, outp);
        }
    }
}

// ============ tensor-core attention: one block per (window, head) ============
#define ATT_SMEM (256 * 80 * 3)
__global__ __launch_bounds__(256) void attn_mma(const float* __restrict__ mask) {
    extern __shared__ __align__(16) char sm[];
    char* Qs = sm;
    char* Ksm = sm + 256 * 80;
    char* Vsm = sm + 2 * 256 * 80;

    int bid = blockIdx.x;
    int wnd = bid / 6;
    int head = bid - wnd * 6;
    int tid = threadIdx.x;

    size_t gbase = (size_t)((wnd * 6 + head) * 256) * 32;
    const uint4* Qg = (const uint4*)(g_q + gbase);
    const uint4* Kg = (const uint4*)(g_k + gbase);
    const uint4* Vg = (const uint4*)(g_v + gbase);
    for (int i = tid; i < 1024; i += 256) {
        int row = i >> 2, c4 = i & 3;
        int off = row * 80 + c4 * 16;
        *(uint4*)(Qs + off)  = Qg[i];
        *(uint4*)(Ksm + off) = Kg[i];
        *(uint4*)(Vsm + off) = Vg[i];
    }
    __syncthreads();

    int w = tid >> 5, l = tid & 31;
    u32 sQ = smem_u32(Qs), sK = smem_u32(Ksm), sV = smem_u32(Vsm);
    bool border = ((wnd >> 4) == 15) || ((wnd & 15) == 15);

#pragma unroll 1
    for (int hh = 0; hh < 2; hh++) {
        int qr = hh * 128 + w * 16;
        u32 qa[8];
        LDM4(qa,     sQ + (qr + (l & 15)) * 80 + (l >> 4) * 16);
        LDM4(qa + 4, sQ + (qr + (l & 15)) * 80 + 32 + (l >> 4) * 16);

        float d[32][4];
#pragma unroll
        for (int t = 0; t < 32; t++)
#pragma unroll
            for (int q = 0; q < 4; q++) d[t][q] = 0.0f;

#pragma unroll
        for (int t = 0; t < 32; t++) {
            u32 kb[4];
            LDM4(kb, sK + (t * 8 + (l & 7)) * 80 + (l >> 3) * 16);
            MMA(d[t], qa, kb[0], kb[1]);
            MMA(d[t], qa + 4, kb[2], kb[3]);
        }

        int r0 = qr + (l >> 2);
        const __nv_bfloat16* bA = g_bias6b + head * 65536 + r0 * 256;
        const __nv_bfloat16* bB = bA + 2048;
        const float* mA = mask + (size_t)wnd * 65536 + r0 * 256;
        const float* mB = mA + 2048;

        float sA = 0.0f, sB = 0.0f;
        u32 pbf[16][4];
#pragma unroll
        for (int t = 0; t < 32; t++) {
            int c = t * 8 + 2 * (l & 3);
            float2 aA = __bfloat1622float2(*(const __nv_bfloat162*)(bA + c));
            float2 aB = __bfloat1622float2(*(const __nv_bfloat162*)(bB + c));
            if (border) {
                float2 ma = *(const float2*)(mA + c);
                float2 mb = *(const float2*)(mB + c);
                aA.x += ma.x; aA.y += ma.y;
                aB.x += mb.x; aB.y += mb.y;
            }
            float p0 = __expf(d[t][0] + aA.x);
            float p1 = __expf(d[t][1] + aA.y);
            float p2 = __expf(d[t][2] + aB.x);
            float p3 = __expf(d[t][3] + aB.y);
            sA += p0 + p1;
            sB += p2 + p3;
            int kt = t >> 1, s4 = (t & 1) * 2;
            pbf[kt][s4]     = bfpack(p0, p1);
            pbf[kt][s4 + 1] = bfpack(p2, p3);
        }
        sA += __shfl_xor_sync(0xffffffffu, sA, 1);
        sA += __shfl_xor_sync(0xffffffffu, sA, 2);
        sB += __shfl_xor_sync(0xffffffffu, sB, 1);
        sB += __shfl_xor_sync(0xffffffffu, sB, 2);
        float invA = 1.0f / sA, invB = 1.0f / sB;

        float o[4][4];
#pragma unroll
        for (int nt = 0; nt < 4; nt++)
#pragma unroll
            for (int q = 0; q < 4; q++) o[nt][q] = 0.0f;

#pragma unroll
        for (int kt = 0; kt < 16; kt++) {
            u32 v0[4], v1[4];
            u32 vaddr = sV + (kt * 16 + (l & 7) + ((l >> 3) & 1) * 8) * 80 + (l >> 4) * 16;
            LDM4T(v0, vaddr);
            LDM4T(v1, vaddr + 32);
            MMA(o[0], pbf[kt], v0[0], v0[1]);
            MMA(o[1], pbf[kt], v0[2], v0[3]);
            MMA(o[2], pbf[kt], v1[0], v1[1]);
            MMA(o[3], pbf[kt], v1[2], v1[3]);
        }

        __nv_bfloat16* OA = g_aob + (size_t)(wnd * 256 + r0) * CDIM + head * 32;
        __nv_bfloat16* OB = OA + (size_t)8 * CDIM;
#pragma unroll
        for (int nt = 0; nt < 4; nt++) {
            int c = nt * 8 + 2 * (l & 3);
            *(u32*)(OA + c) = bfpack(o[nt][0] * invA, o[nt][1] * invA);
            *(u32*)(OB + c) = bfpack(o[nt][2] * invB, o[nt][3] * invB);
        }
    }
}

// ============ host launcher ============
extern "C" void kernel_launch(void* const* d_in, const int* in_sizes, int n_in,
                              void* d_out, int out_size) {
    const float* x     = (const float*)d_in[0];
    const int*   rpi   = (const int*)d_in[1];
    const float* mask  = (const float*)d_in[2];
    const float* n1g   = (const float*)d_in[3];
    const float* n1b   = (const float*)d_in[4];
    const float* qkvw  = (const float*)d_in[5];
    const float* qkvb  = (const float*)d_in[6];
    const float* rpb   = (const float*)d_in[7];
    const float* projw = (const float*)d_in[8];
    const float* projb = (const float*)d_in[9];
    const float* n2g   = (const float*)d_in[10];
    const float* n2b   = (const float*)d_in[11];
    const float* fc1w  = (const float*)d_in[12];
    const float* fc1b  = (const float*)d_in[13];
    const float* fc2w  = (const float*)d_in[14];
    const float* fc2b  = (const float*)d_in[15];
    float* out = (float*)d_out;

    cudaFuncSetAttribute(attn_mma, cudaFuncAttributeMaxDynamicSharedMemorySize, ATT_SMEM);
    cudaFuncSetAttribute(tmmaA<0>, cudaFuncAttributeMaxDynamicSharedMemorySize, ARES_SMEM);
    cudaFuncSetAttribute(tmmaA<1>, cudaFuncAttributeMaxDynamicSharedMemorySize, ARES_SMEM);
    cudaFuncSetAttribute(tmmaA<2>, cudaFuncAttributeMaxDynamicSharedMemorySize, ARES_SMEM);

    transw_all<<<1728, 256>>>(qkvw, projw, fc1w, fc2w);
    bias6_kernel<<<1536, 256>>>(rpi, rpb);

    ln_kernel<<<512, 256>>>(x, n1g, n1b, 1);                            // LN1 + shift + partition
    tmmaA<0><<<512, 256, ARES_SMEM>>>(qkvb, nullptr, nullptr, 9);       // QKV -> q/k/v bf16
    attn_mma<<<1536, 256, ATT_SMEM>>>(mask);                            // attention -> g_aob
    tmmaA<1><<<512, 256, ARES_SMEM>>>(projb, x, nullptr, 3);            // proj + reverse + resid
    ln_kernel<<<512, 256>>>(x, n2g, n2b, 0);                            // LN2 (reads g_xr)
    tmmaA<2><<<512, 256, ARES_SMEM>>>(fc1b, nullptr, nullptr, 12);      // fc1 + GELU -> g_hb
    tmmaF<<<512, 256>>>(fc2b, out);                                     // fc2 + resid -> out
}

// round 13
// speedup vs baseline: 4.6499x; 1.0818x over previous
#include <cuda_runtime.h>
#include <cuda_bf16.h>
#include <math.h>
#include <stdint.h>

#define LTOK 65536
#define CDIM 192
#define HIDD 768

typedef unsigned long long ull;
typedef unsigned int u32;

// ---------------- scratch (static device globals; no allocation) ----------------
__device__ __nv_bfloat16 g_xwb[LTOK * CDIM];   // LN1 out (window order) / LN2 out (token order)
__device__ __nv_bfloat16 g_q[LTOK * CDIM];     // [win,head,n,d] bf16 (q pre-scaled)
__device__ __nv_bfloat16 g_k[LTOK * CDIM];
__device__ __nv_bfloat16 g_v[LTOK * CDIM];
__device__ __nv_bfloat16 g_aob[LTOK * CDIM];   // attention out, window order, bf16
__device__ float g_xr[LTOK * CDIM];            // first residual, token order, fp32
__device__ __nv_bfloat16 g_hb[LTOK * HIDD];    // MLP hidden, bf16
__device__ __nv_bfloat16 g_bias6b[6 * 256 * 256];   // rel-pos bias, bf16
// transposed bf16 weights: [N, K] row-major
__device__ __nv_bfloat16 g_wqkv[576 * 192];
__device__ __nv_bfloat16 g_wproj[192 * 192];
__device__ __nv_bfloat16 g_wfc1[768 * 192];
__device__ __nv_bfloat16 g_wfc2[192 * 768];

// ---------------- mma.sync helpers ----------------
__device__ __forceinline__ u32 smem_u32(const void* p) {
    u32 a;
    asm("{ .reg .u64 t; cvta.to.shared.u64 t, %1; cvt.u32.u64 %0, t; }" : "=r"(a) : "l"(p));
    return a;
}
#define LDM4(R, addr)                                                            \
    asm volatile("ldmatrix.sync.aligned.m8n8.x4.shared.b16 {%0,%1,%2,%3}, [%4];" \
        : "=r"((R)[0]), "=r"((R)[1]), "=r"((R)[2]), "=r"((R)[3]) : "r"(addr))

#define LDM4T(R, addr)                                                           \
    asm volatile("ldmatrix.sync.aligned.m8n8.x4.trans.shared.b16 {%0,%1,%2,%3}, [%4];" \
        : "=r"((R)[0]), "=r"((R)[1]), "=r"((R)[2]), "=r"((R)[3]) : "r"(addr))

#define MMA(dd, A, B0, B1)                                                       \
    asm volatile("mma.sync.aligned.m16n8k16.row.col.f32.bf16.bf16.f32 "          \
        "{%0,%1,%2,%3}, {%4,%5,%6,%7}, {%8,%9}, {%0,%1,%2,%3};"                  \
        : "+f"((dd)[0]), "+f"((dd)[1]), "+f"((dd)[2]), "+f"((dd)[3])             \
        : "r"((A)[0]), "r"((A)[1]), "r"((A)[2]), "r"((A)[3]), "r"(B0), "r"(B1))

__device__ __forceinline__ u32 bfpack(float a, float b) {
    __nv_bfloat162 h = __floats2bfloat162_rn(a, b);
    return *(u32*)&h;
}

__device__ __forceinline__ float gelu_exact(float x) {
    return 0.5f * x * (1.0f + erff(x * 0.70710678118654752f));
}

// ============ all weight transposes fused: Wt[n*K+k] = W[k*N+n] ============
__global__ void transw_all(const float* __restrict__ qkvw, const float* __restrict__ projw,
                           const float* __restrict__ fc1w, const float* __restrict__ fc2w) {
    int i = blockIdx.x * 256 + threadIdx.x;
    const float* W; __nv_bfloat16* Wt; int K, N, j;
    if (i < 110592)      { j = i;          W = qkvw; Wt = g_wqkv;  K = 192; N = 576; }
    else if (i < 147456) { j = i - 110592; W = projw; Wt = g_wproj; K = 192; N = 192; }
    else if (i < 294912) { j = i - 147456; W = fc1w; Wt = g_wfc1;  K = 192; N = 768; }
    else                 { j = i - 294912; W = fc2w; Wt = g_wfc2;  K = 768; N = 192; }
    int n = j / K, k = j - n * K;
    Wt[j] = __float2bfloat16_rn(W[k * N + n]);
}

// ============ relative position bias gather (bf16) ============
__global__ void bias6_kernel(const int* __restrict__ rpi, const float* __restrict__ rpb) {
    int id = blockIdx.x * 256 + threadIdx.x;
    int head = id >> 16;
    int nm = id & 65535;
    g_bias6b[id] = __float2bfloat16_rn(rpb[rpi[nm] * 6 + head]);
}

// ============ LayerNorm: warp-per-token, bf16 out ============
__global__ __launch_bounds__(256) void ln_kernel(const float* __restrict__ xin,
                                                 const float* __restrict__ gw,
                                                 const float* __restrict__ bw, int mode) {
    int gwid = (blockIdx.x * 256 + threadIdx.x) >> 5;
    int l = threadIdx.x & 31;
    int nwarp = (gridDim.x * 256) >> 5;

    float gg[6], bb[6];
#pragma unroll
    for (int j = 0; j < 6; j++) { gg[j] = gw[l + 32 * j]; bb[j] = bw[l + 32 * j]; }

    const float* src = mode ? xin : g_xr;
    for (int s = gwid; s < LTOK; s += nwarp) {
        const float* in = src + (size_t)s * CDIM;
        float v[6], sum = 0.0f, sq = 0.0f;
#pragma unroll
        for (int j = 0; j < 6; j++) {
            v[j] = in[l + 32 * j];
            sum += v[j];
            sq += v[j] * v[j];
        }
#pragma unroll
        for (int o = 16; o; o >>= 1) {
            sum += __shfl_xor_sync(0xffffffffu, sum, o);
            sq  += __shfl_xor_sync(0xffffffffu, sq, o);
        }
        float mean = sum * (1.0f / CDIM);
        float var = sq * (1.0f / CDIM) - mean * mean;
        float rs = rsqrtf(var + 1e-5f);
        int r;
        if (mode) {
            int h = s >> 8, w = s & 255;
            int i = (h + 248) & 255, j = (w + 248) & 255;
            r = (((i >> 4) << 4) + (j >> 4)) * 256 + ((i & 15) << 4) + (j & 15);
        } else {
            r = s;
        }
        __nv_bfloat16* dst = g_xwb + (size_t)r * CDIM;
#pragma unroll
        for (int j = 0; j < 6; j++)
            dst[l + 32 * j] = __float2bfloat16_rn((v[j] - mean) * rs * gg[j] + bb[j]);
    }
}

// ============ epilogue pair-store ============
template <int MODE>
__device__ __forceinline__ void store2(int r, int n, float2 v,
                                       const float* __restrict__ aux,
                                       float* __restrict__ outp) {
    if (MODE == 0) {
        int which = n / 192;
        int rem = n - which * 192;
        int head = rem >> 5, dd = rem & 31;
        int wnd = r >> 8, nn = r & 255;
        __nv_bfloat16* dst = ((which == 0) ? g_q : (which == 1) ? g_k : g_v)
                             + (size_t)((wnd * 6 + head) * 256 + nn) * 32 + dd;
        if (which == 0) {
            v.x *= 0.17677669529663687f;
            v.y *= 0.17677669529663687f;
        }
        *(u32*)dst = bfpack(v.x, v.y);
    } else if (MODE == 1) {
        int wnd = r >> 8, nn = r & 255;
        int i_ = ((wnd >> 4) << 4) + (nn >> 4);
        int j_ = ((wnd & 15) << 4) + (nn & 15);
        int s = (((i_ + 8) & 255) << 8) + ((j_ + 8) & 255);
        float2 a = *(const float2*)(aux + (size_t)s * CDIM + n);
        v.x += a.x; v.y += a.y;
        *(float2*)(g_xr + (size_t)s * CDIM + n) = v;
    } else if (MODE == 2) {
        *(u32*)(g_hb + (size_t)r * HIDD + n) = bfpack(gelu_exact(v.x), gelu_exact(v.y));
    } else {
        float2 a = *(const float2*)(g_xr + (size_t)r * CDIM + n);
        v.x += a.x; v.y += a.y;
        *(float2*)(outp + (size_t)r * CDIM + n) = v;
    }
}

// ============ A-resident GEMM for K=192, double-buffered B ============
// A tile (128x192 bf16) loaded once; 24 a-frags in registers.
// Per n-tile: store prefetched B -> alt buffer, prefetch nt+2, MMA on cur, ONE sync.
#define ARES_SMEM (128 * 400 + 2 * 64 * 400)
template <int MODE>
__global__ __launch_bounds__(256) void tmmaA(const float* __restrict__ bias,
                                             const float* __restrict__ aux,
                                             float* __restrict__ outp, int NT) {
    extern __shared__ __align__(16) char sm[];
    char* As = sm;                       // 128 * 400
    char* Bs = sm + 128 * 400;           // 2 buffers * 64 * 400

    const __nv_bfloat16* Ag = (MODE == 1) ? g_aob : g_xwb;
    const __nv_bfloat16* Wt = (MODE == 0) ? g_wqkv : (MODE == 1) ? g_wproj : g_wfc1;

    int tid = threadIdx.x;
    int w = tid >> 5, l = tid & 31;
    int wm = w & 3, wn = w >> 2;
    int m0 = blockIdx.x * 128;

    // prefetch B tile 0
    uint4 pf[6];
#pragma unroll
    for (int j = 0; j < 6; j++) {
        int id = tid + j * 256;
        int row = id / 24, ch = id - row * 24;
        pf[j] = *(const uint4*)(Wt + (size_t)row * 192 + ch * 8);
    }
    // load A tile
#pragma unroll
    for (int j = 0; j < 12; j++) {
        int id = tid + j * 256;
        int row = id / 24, ch = id - row * 24;
        *(uint4*)(As + row * 400 + ch * 16) =
            *(const uint4*)(Ag + (size_t)(m0 + row) * 192 + ch * 8);
    }
    // store B tile 0 into buffer 0
#pragma unroll
    for (int j = 0; j < 6; j++) {
        int id = tid + j * 256;
        int row = id / 24, ch = id - row * 24;
        *(uint4*)(Bs + row * 400 + ch * 16) = pf[j];
    }
    __syncthreads();

    // a-fragments in registers
    u32 sa = smem_u32(As), sb0 = smem_u32(Bs);
    u32 areg[2][12][4];
#pragma unroll
    for (int mt = 0; mt < 2; mt++) {
        u32 base = sa + (wm * 32 + mt * 16 + (l & 15)) * 400 + (l >> 4) * 16;
#pragma unroll
        for (int ks = 0; ks < 12; ks++) LDM4(areg[mt][ks], base + ks * 32);
    }

    // prefetch tile 1
    if (NT > 1) {
        const __nv_bfloat16* Wn = Wt + (size_t)64 * 192;
#pragma unroll
        for (int j = 0; j < 6; j++) {
            int id = tid + j * 256;
            int row = id / 24, ch = id - row * 24;
            pf[j] = *(const uint4*)(Wn + (size_t)row * 192 + ch * 8);
        }
    }

    u32 bOff = (wn * 32 + (l & 7) + ((l >> 3) & 1) * 8) * 400 + (l >> 4) * 16;
    int lq = l >> 2, lr = l & 3;

    for (int nt = 0; nt < NT; nt++) {
        int cur = nt & 1;
        // 1. store prefetched tile nt+1 into alt buffer
        if (nt + 1 < NT) {
            char* Bn = Bs + (1 - cur) * 25600;
#pragma unroll
            for (int j = 0; j < 6; j++) {
                int id = tid + j * 256;
                int row = id / 24, ch = id - row * 24;
                *(uint4*)(Bn + row * 400 + ch * 16) = pf[j];
            }
        }
        // 2. prefetch tile nt+2
        if (nt + 2 < NT) {
            const __nv_bfloat16* Wn = Wt + (size_t)(nt + 2) * 64 * 192;
#pragma unroll
            for (int j = 0; j < 6; j++) {
                int id = tid + j * 256;
                int row = id / 24, ch = id - row * 24;
                pf[j] = *(const uint4*)(Wn + (size_t)row * 192 + ch * 8);
            }
        }
        // 3. MMAs on current buffer
        u32 bBase = sb0 + cur * 25600 + bOff;
        float d[2][4][4];
#pragma unroll
        for (int mt = 0; mt < 2; mt++)
#pragma unroll
            for (int nj = 0; nj < 4; nj++)
#pragma unroll
                for (int q = 0; q < 4; q++) d[mt][nj][q] = 0.0f;

#pragma unroll
        for (int ks = 0; ks < 12; ks++) {
            u32 r0[4], r1[4];
            LDM4(r0, bBase + ks * 32);
            LDM4(r1, bBase + 6400 + ks * 32);
            MMA(d[0][0], areg[0][ks], r0[0], r0[2]);
            MMA(d[0][1], areg[0][ks], r0[1], r0[3]);
            MMA(d[0][2], areg[0][ks], r1[0], r1[2]);
            MMA(d[0][3], areg[0][ks], r1[1], r1[3]);
            MMA(d[1][0], areg[1][ks], r0[0], r0[2]);
            MMA(d[1][1], areg[1][ks], r0[1], r0[3]);
            MMA(d[1][2], areg[1][ks], r1[0], r1[2]);
            MMA(d[1][3], areg[1][ks], r1[1], r1[3]);
        }
        // 4. epilogue
#pragma unroll
        for (int mt = 0; mt < 2; mt++) {
            int ra = m0 + wm * 32 + mt * 16 + lq;
            int rb = ra + 8;
#pragma unroll
            for (int nj = 0; nj < 4; nj++) {
                int ng = nt * 64 + wn * 32 + nj * 8 + lr * 2;
                float2 b2 = *(const float2*)(bias + ng);
                float2 v0 = make_float2(d[mt][nj][0] + b2.x, d[mt][nj][1] + b2.y);
                float2 v1 = make_float2(d[mt][nj][2] + b2.x, d[mt][nj][3] + b2.y);
                store2<MODE>(ra, ng, v0, aux, outp);
                store2<MODE>(rb, ng, v1, aux, outp);
            }
        }
        __syncthreads();
    }
}

// ============ fc2 GEMM: K=768, BM=128, BN=192 single pass, double-buffered ============
// layout: A0@0 (10240), B0@10240 (15360), A1@25600, B1@35840 ; total 51200
#define FC2_SMEM (2 * (128 * 80 + 192 * 80))
__global__ __launch_bounds__(256) void tmmaF(const float* __restrict__ bias,
                                             float* __restrict__ outp) {
    extern __shared__ __align__(16) char smF[];
    int tid = threadIdx.x;
    int w = tid >> 5, l = tid & 31;
    int wm = w & 3, wn = w >> 2;   // 4 x 2 warps; warp tile 32 x 96
    int m0 = blockIdx.x * 128;

    const __nv_bfloat16* Ag = g_hb;
    const __nv_bfloat16* Wt = g_wfc2;

    u32 s0 = smem_u32(smF);
    u32 aOff = (wm * 32 + (l & 7) + ((l >> 3) & 1) * 8) * 80 + (l >> 4) * 16;
    u32 bOff = 10240 + (wn * 96 + (l & 7) + ((l >> 3) & 1) * 8) * 80 + (l >> 4) * 16;

    float d[2][12][4];
#pragma unroll
    for (int mt = 0; mt < 2; mt++)
#pragma unroll
        for (int nj = 0; nj < 12; nj++)
#pragma unroll
            for (int q = 0; q < 4; q++) d[mt][nj][q] = 0.0f;

    uint4 pa[2], pb[3];
#pragma unroll
    for (int j = 0; j < 2; j++) {
        int id = tid + j * 256;
        pa[j] = *(const uint4*)(Ag + (size_t)(m0 + (id >> 2)) * HIDD + (id & 3) * 8);
    }
#pragma unroll
    for (int j = 0; j < 3; j++) {
        int id = tid + j * 256;
        pb[j] = *(const uint4*)(Wt + (size_t)(id >> 2) * HIDD + (id & 3) * 8);
    }
    // store k-slab 0 into buffer 0
#pragma unroll
    for (int j = 0; j < 2; j++) {
        int id = tid + j * 256;
        *(uint4*)(smF + (id >> 2) * 80 + (id & 3) * 16) = pa[j];
    }
#pragma unroll
    for (int j = 0; j < 3; j++) {
        int id = tid + j * 256;
        *(uint4*)(smF + 10240 + (id >> 2) * 80 + (id & 3) * 16) = pb[j];
    }
    __syncthreads();
    // prefetch slab 1
    {
#pragma unroll
        for (int j = 0; j < 2; j++) {
            int id = tid + j * 256;
            pa[j] = *(const uint4*)(Ag + (size_t)(m0 + (id >> 2)) * HIDD + 32 + (id & 3) * 8);
        }
#pragma unroll
        for (int j = 0; j < 3; j++) {
            int id = tid + j * 256;
            pb[j] = *(const uint4*)(Wt + (size_t)(id >> 2) * HIDD + 32 + (id & 3) * 8);
        }
    }

    for (int kt = 0; kt < 24; kt++) {
        int cur = kt & 1;
        // 1. store prefetched slab kt+1 into alt buffer
        if (kt + 1 < 24) {
            char* base = smF + (1 - cur) * 25600;
#pragma unroll
            for (int j = 0; j < 2; j++) {
                int id = tid + j * 256;
                *(uint4*)(base + (id >> 2) * 80 + (id & 3) * 16) = pa[j];
            }
#pragma unroll
            for (int j = 0; j < 3; j++) {
                int id = tid + j * 256;
                *(uint4*)(base + 10240 + (id >> 2) * 80 + (id & 3) * 16) = pb[j];
            }
        }
        // 2. prefetch slab kt+2
        if (kt + 2 < 24) {
            int kc = (kt + 2) * 32;
#pragma unroll
            for (int j = 0; j < 2; j++) {
                int id = tid + j * 256;
                pa[j] = *(const uint4*)(Ag + (size_t)(m0 + (id >> 2)) * HIDD + kc + (id & 3) * 8);
            }
#pragma unroll
            for (int j = 0; j < 3; j++) {
                int id = tid + j * 256;
                pb[j] = *(const uint4*)(Wt + (size_t)(id >> 2) * HIDD + kc + (id & 3) * 8);
            }
        }
        // 3. MMAs on current buffer
        u32 aBase = s0 + cur * 25600 + aOff;
        u32 bBase = s0 + cur * 25600 + bOff;
#pragma unroll
        for (int ks = 0; ks < 2; ks++) {
            u32 a0[4], a1[4];
            LDM4(a0, aBase + ks * 32);
            LDM4(a1, aBase + 1280 + ks * 32);
#pragma unroll
            for (int g = 0; g < 6; g++) {
                u32 rg[4];
                LDM4(rg, bBase + g * 1280 + ks * 32);
                MMA(d[0][2 * g],     a0, rg[0], rg[2]);
                MMA(d[0][2 * g + 1], a0, rg[1], rg[3]);
                MMA(d[1][2 * g],     a1, rg[0], rg[2]);
                MMA(d[1][2 * g + 1], a1, rg[1], rg[3]);
            }
        }
        __syncthreads();
    }

    int lq = l >> 2, lr = l & 3;
#pragma unroll
    for (int mt = 0; mt < 2; mt++) {
        int ra = m0 + wm * 32 + mt * 16 + lq;
        int rb = ra + 8;
#pragma unroll
        for (int nj = 0; nj < 12; nj++) {
            int ng = wn * 96 + nj * 8 + lr * 2;
            float2 b2 = *(const float2*)(bias + ng);
            float2 v0 = make_float2(d[mt][nj][0] + b2.x, d[mt][nj][1] + b2.y);
            float2 v1 = make_float2(d[mt][nj][2] + b2.x, d[mt][nj][3] + b2.y);
            store2<3>(ra, ng, v0, nullptr, outp);
            store2<3>(rb, ng, v1, nullptr, outp);
        }
    }
}

// ============ tensor-core attention: one block per (window, head) ============
// 8 warps, two 128-query passes; keys split into two 128-halves to cut registers
// (sum + unnormalized O accumulate across halves — identical math, no rescale).
#define ATT_SMEM (256 * 80 * 3)
__global__ __launch_bounds__(256, 2) void attn_mma(const float* __restrict__ mask) {
    extern __shared__ __align__(16) char sm[];
    char* Qs = sm;
    char* Ksm = sm + 256 * 80;
    char* Vsm = sm + 2 * 256 * 80;

    int bid = blockIdx.x;
    int wnd = bid / 6;
    int head = bid - wnd * 6;
    int tid = threadIdx.x;

    size_t gbase = (size_t)((wnd * 6 + head) * 256) * 32;
    const uint4* Qg = (const uint4*)(g_q + gbase);
    const uint4* Kg = (const uint4*)(g_k + gbase);
    const uint4* Vg = (const uint4*)(g_v + gbase);
    for (int i = tid; i < 1024; i += 256) {
        int row = i >> 2, c4 = i & 3;
        int off = row * 80 + c4 * 16;
        *(uint4*)(Qs + off)  = Qg[i];
        *(uint4*)(Ksm + off) = Kg[i];
        *(uint4*)(Vsm + off) = Vg[i];
    }
    __syncthreads();

    int w = tid >> 5, l = tid & 31;
    u32 sQ = smem_u32(Qs), sK = smem_u32(Ksm), sV = smem_u32(Vsm);
    bool border = ((wnd >> 4) == 15) || ((wnd & 15) == 15);

#pragma unroll 1
    for (int hh = 0; hh < 2; hh++) {
        int qr = hh * 128 + w * 16;
        u32 qa[8];
        LDM4(qa,     sQ + (qr + (l & 15)) * 80 + (l >> 4) * 16);
        LDM4(qa + 4, sQ + (qr + (l & 15)) * 80 + 32 + (l >> 4) * 16);

        int r0 = qr + (l >> 2);
        const __nv_bfloat16* bA = g_bias6b + head * 65536 + r0 * 256;
        const __nv_bfloat16* bB = bA + 2048;
        const float* mA = mask + (size_t)wnd * 65536 + r0 * 256;
        const float* mB = mA + 2048;

        float sA = 0.0f, sB = 0.0f;
        float o[4][4];
#pragma unroll
        for (int nt = 0; nt < 4; nt++)
#pragma unroll
            for (int q = 0; q < 4; q++) o[nt][q] = 0.0f;

#pragma unroll 1
        for (int kh = 0; kh < 2; kh++) {
            int kb0 = kh * 128;
            float d[16][4];
#pragma unroll
            for (int t = 0; t < 16; t++)
#pragma unroll
                for (int q = 0; q < 4; q++) d[t][q] = 0.0f;

#pragma unroll
            for (int t = 0; t < 16; t++) {
                u32 kb[4];
                LDM4(kb, sK + (kb0 + t * 8 + (l & 7)) * 80 + (l >> 3) * 16);
                MMA(d[t], qa, kb[0], kb[1]);
                MMA(d[t], qa + 4, kb[2], kb[3]);
            }

            u32 pbf[8][4];
#pragma unroll
            for (int t = 0; t < 16; t++) {
                int c = kb0 + t * 8 + 2 * (l & 3);
                float2 aA = __bfloat1622float2(*(const __nv_bfloat162*)(bA + c));
                float2 aB = __bfloat1622float2(*(const __nv_bfloat162*)(bB + c));
                if (border) {
                    float2 ma = *(const float2*)(mA + c);
                    float2 mb = *(const float2*)(mB + c);
                    aA.x += ma.x; aA.y += ma.y;
                    aB.x += mb.x; aB.y += mb.y;
                }
                float p0 = __expf(d[t][0] + aA.x);
                float p1 = __expf(d[t][1] + aA.y);
                float p2 = __expf(d[t][2] + aB.x);
                float p3 = __expf(d[t][3] + aB.y);
                sA += p0 + p1;
                sB += p2 + p3;
                int kt = t >> 1, s4 = (t & 1) * 2;
                pbf[kt][s4]     = bfpack(p0, p1);
                pbf[kt][s4 + 1] = bfpack(p2, p3);
            }

#pragma unroll
            for (int kt = 0; kt < 8; kt++) {
                u32 v0[4], v1[4];
                u32 vaddr = sV + (kb0 + kt * 16 + (l & 7) + ((l >> 3) & 1) * 8) * 80 + (l >> 4) * 16;
                LDM4T(v0, vaddr);
                LDM4T(v1, vaddr + 32);
                MMA(o[0], pbf[kt], v0[0], v0[1]);
                MMA(o[1], pbf[kt], v0[2], v0[3]);
                MMA(o[2], pbf[kt], v1[0], v1[1]);
                MMA(o[3], pbf[kt], v1[2], v1[3]);
            }
        }

        sA += __shfl_xor_sync(0xffffffffu, sA, 1);
        sA += __shfl_xor_sync(0xffffffffu, sA, 2);
        sB += __shfl_xor_sync(0xffffffffu, sB, 1);
        sB += __shfl_xor_sync(0xffffffffu, sB, 2);
        float invA = 1.0f / sA, invB = 1.0f / sB;

        __nv_bfloat16* OA = g_aob + (size_t)(wnd * 256 + r0) * CDIM + head * 32;
        __nv_bfloat16* OB = OA + (size_t)8 * CDIM;
#pragma unroll
        for (int nt = 0; nt < 4; nt++) {
            int c = nt * 8 + 2 * (l & 3);
            *(u32*)(OA + c) = bfpack(o[nt][0] * invA, o[nt][1] * invA);
            *(u32*)(OB + c) = bfpack(o[nt][2] * invB, o[nt][3] * invB);
        }
    }
}

// ============ host launcher ============
extern "C" void kernel_launch(void* const* d_in, const int* in_sizes, int n_in,
                              void* d_out, int out_size) {
    const float* x     = (const float*)d_in[0];
    const int*   rpi   = (const int*)d_in[1];
    const float* mask  = (const float*)d_in[2];
    const float* n1g   = (const float*)d_in[3];
    const float* n1b   = (const float*)d_in[4];
    const float* qkvw  = (const float*)d_in[5];
    const float* qkvb  = (const float*)d_in[6];
    const float* rpb   = (const float*)d_in[7];
    const float* projw = (const float*)d_in[8];
    const float* projb = (const float*)d_in[9];
    const float* n2g   = (const float*)d_in[10];
    const float* n2b   = (const float*)d_in[11];
    const float* fc1w  = (const float*)d_in[12];
    const float* fc1b  = (const float*)d_in[13];
    const float* fc2w  = (const float*)d_in[14];
    const float* fc2b  = (const float*)d_in[15];
    float* out = (float*)d_out;

    cudaFuncSetAttribute(attn_mma, cudaFuncAttributeMaxDynamicSharedMemorySize, ATT_SMEM);
    cudaFuncSetAttribute(tmmaA<0>, cudaFuncAttributeMaxDynamicSharedMemorySize, ARES_SMEM);
    cudaFuncSetAttribute(tmmaA<1>, cudaFuncAttributeMaxDynamicSharedMemorySize, ARES_SMEM);
    cudaFuncSetAttribute(tmmaA<2>, cudaFuncAttributeMaxDynamicSharedMemorySize, ARES_SMEM);
    cudaFuncSetAttribute(tmmaF, cudaFuncAttributeMaxDynamicSharedMemorySize, FC2_SMEM);

    transw_all<<<1728, 256>>>(qkvw, projw, fc1w, fc2w);
    bias6_kernel<<<1536, 256>>>(rpi, rpb);

    ln_kernel<<<512, 256>>>(x, n1g, n1b, 1);                            // LN1 + shift + partition
    tmmaA<0><<<512, 256, ARES_SMEM>>>(qkvb, nullptr, nullptr, 9);       // QKV -> q/k/v bf16
    attn_mma<<<1536, 256, ATT_SMEM>>>(mask);                            // attention -> g_aob
    tmmaA<1><<<512, 256, ARES_SMEM>>>(projb, x, nullptr, 3);            // proj + reverse + resid
    ln_kernel<<<512, 256>>>(x, n2g, n2b, 0);                            // LN2 (reads g_xr)
    tmmaA<2><<<512, 256, ARES_SMEM>>>(fc1b, nullptr, nullptr, 12);      // fc1 + GELU -> g_hb
    tmmaF<<<512, 256, FC2_SMEM>>>(fc2b, out);                           // fc2 + resid -> out
}

// round 14
// speedup vs baseline: 4.9654x; 1.0679x over previous
#include <cuda_runtime.h>
#include <cuda_bf16.h>
#include <math.h>
#include <stdint.h>

#define LTOK 65536
#define CDIM 192
#define HIDD 768

typedef unsigned long long ull;
typedef unsigned int u32;

// ---------------- scratch (static device globals; no allocation) ----------------
__device__ __nv_bfloat16 g_xwb[LTOK * CDIM];   // LN1 out (window order) / LN2 out (token order)
__device__ __nv_bfloat16 g_q[LTOK * CDIM];     // [win,head,n,d] bf16 (q pre-scaled)
__device__ __nv_bfloat16 g_k[LTOK * CDIM];
__device__ __nv_bfloat16 g_v[LTOK * CDIM];
__device__ __nv_bfloat16 g_aob[LTOK * CDIM];   // attention out, window order, bf16
__device__ float g_xr[LTOK * CDIM];            // first residual, token order, fp32
__device__ __nv_bfloat16 g_hb[LTOK * HIDD];    // MLP hidden, bf16
__device__ __nv_bfloat16 g_bias6b[6 * 256 * 256];   // rel-pos bias, bf16
// transposed bf16 weights: [N, K] row-major
__device__ __nv_bfloat16 g_wqkv[576 * 192];
__device__ __nv_bfloat16 g_wproj[192 * 192];
__device__ __nv_bfloat16 g_wfc1[768 * 192];
__device__ __nv_bfloat16 g_wfc2[192 * 768];

// ---------------- mma.sync helpers ----------------
__device__ __forceinline__ u32 smem_u32(const void* p) {
    u32 a;
    asm("{ .reg .u64 t; cvta.to.shared.u64 t, %1; cvt.u32.u64 %0, t; }" : "=r"(a) : "l"(p));
    return a;
}
#define LDM4(R, addr)                                                            \
    asm volatile("ldmatrix.sync.aligned.m8n8.x4.shared.b16 {%0,%1,%2,%3}, [%4];" \
        : "=r"((R)[0]), "=r"((R)[1]), "=r"((R)[2]), "=r"((R)[3]) : "r"(addr))

#define LDM4T(R, addr)                                                           \
    asm volatile("ldmatrix.sync.aligned.m8n8.x4.trans.shared.b16 {%0,%1,%2,%3}, [%4];" \
        : "=r"((R)[0]), "=r"((R)[1]), "=r"((R)[2]), "=r"((R)[3]) : "r"(addr))

#define MMA(dd, A, B0, B1)                                                       \
    asm volatile("mma.sync.aligned.m16n8k16.row.col.f32.bf16.bf16.f32 "          \
        "{%0,%1,%2,%3}, {%4,%5,%6,%7}, {%8,%9}, {%0,%1,%2,%3};"                  \
        : "+f"((dd)[0]), "+f"((dd)[1]), "+f"((dd)[2]), "+f"((dd)[3])             \
        : "r"((A)[0]), "r"((A)[1]), "r"((A)[2]), "r"((A)[3]), "r"(B0), "r"(B1))

__device__ __forceinline__ u32 bfpack(float a, float b) {
    __nv_bfloat162 h = __floats2bfloat162_rn(a, b);
    return *(u32*)&h;
}

__device__ __forceinline__ float gelu_exact(float x) {
    return 0.5f * x * (1.0f + erff(x * 0.70710678118654752f));
}

// ============ all weight transposes fused: Wt[n*K+k] = W[k*N+n] ============
__global__ void transw_all(const float* __restrict__ qkvw, const float* __restrict__ projw,
                           const float* __restrict__ fc1w, const float* __restrict__ fc2w) {
    int i = blockIdx.x * 256 + threadIdx.x;
    const float* W; __nv_bfloat16* Wt; int K, N, j;
    if (i < 110592)      { j = i;          W = qkvw; Wt = g_wqkv;  K = 192; N = 576; }
    else if (i < 147456) { j = i - 110592; W = projw; Wt = g_wproj; K = 192; N = 192; }
    else if (i < 294912) { j = i - 147456; W = fc1w; Wt = g_wfc1;  K = 192; N = 768; }
    else                 { j = i - 294912; W = fc2w; Wt = g_wfc2;  K = 768; N = 192; }
    int n = j / K, k = j - n * K;
    Wt[j] = __float2bfloat16_rn(W[k * N + n]);
}

// ============ relative position bias gather (bf16) ============
__global__ void bias6_kernel(const int* __restrict__ rpi, const float* __restrict__ rpb) {
    int id = blockIdx.x * 256 + threadIdx.x;
    int head = id >> 16;
    int nm = id & 65535;
    g_bias6b[id] = __float2bfloat16_rn(rpb[rpi[nm] * 6 + head]);
}

// ============ LayerNorm: warp-per-token, bf16 out ============
__global__ __launch_bounds__(256) void ln_kernel(const float* __restrict__ xin,
                                                 const float* __restrict__ gw,
                                                 const float* __restrict__ bw, int mode) {
    int gwid = (blockIdx.x * 256 + threadIdx.x) >> 5;
    int l = threadIdx.x & 31;
    int nwarp = (gridDim.x * 256) >> 5;

    float gg[6], bb[6];
#pragma unroll
    for (int j = 0; j < 6; j++) { gg[j] = gw[l + 32 * j]; bb[j] = bw[l + 32 * j]; }

    const float* src = mode ? xin : g_xr;
    for (int s = gwid; s < LTOK; s += nwarp) {
        const float* in = src + (size_t)s * CDIM;
        float v[6], sum = 0.0f, sq = 0.0f;
#pragma unroll
        for (int j = 0; j < 6; j++) {
            v[j] = in[l + 32 * j];
            sum += v[j];
            sq += v[j] * v[j];
        }
#pragma unroll
        for (int o = 16; o; o >>= 1) {
            sum += __shfl_xor_sync(0xffffffffu, sum, o);
            sq  += __shfl_xor_sync(0xffffffffu, sq, o);
        }
        float mean = sum * (1.0f / CDIM);
        float var = sq * (1.0f / CDIM) - mean * mean;
        float rs = rsqrtf(var + 1e-5f);
        int r;
        if (mode) {
            int h = s >> 8, w = s & 255;
            int i = (h + 248) & 255, j = (w + 248) & 255;
            r = (((i >> 4) << 4) + (j >> 4)) * 256 + ((i & 15) << 4) + (j & 15);
        } else {
            r = s;
        }
        __nv_bfloat16* dst = g_xwb + (size_t)r * CDIM;
#pragma unroll
        for (int j = 0; j < 6; j++)
            dst[l + 32 * j] = __float2bfloat16_rn((v[j] - mean) * rs * gg[j] + bb[j]);
    }
}

// ============ epilogue pair-store ============
template <int MODE>
__device__ __forceinline__ void store2(int r, int n, float2 v,
                                       const float* __restrict__ aux,
                                       float* __restrict__ outp) {
    if (MODE == 0) {
        int which = n / 192;
        int rem = n - which * 192;
        int head = rem >> 5, dd = rem & 31;
        int wnd = r >> 8, nn = r & 255;
        __nv_bfloat16* dst = ((which == 0) ? g_q : (which == 1) ? g_k : g_v)
                             + (size_t)((wnd * 6 + head) * 256 + nn) * 32 + dd;
        if (which == 0) {
            v.x *= 0.17677669529663687f;
            v.y *= 0.17677669529663687f;
        }
        *(u32*)dst = bfpack(v.x, v.y);
    } else if (MODE == 1) {
        int wnd = r >> 8, nn = r & 255;
        int i_ = ((wnd >> 4) << 4) + (nn >> 4);
        int j_ = ((wnd & 15) << 4) + (nn & 15);
        int s = (((i_ + 8) & 255) << 8) + ((j_ + 8) & 255);
        float2 a = *(const float2*)(aux + (size_t)s * CDIM + n);
        v.x += a.x; v.y += a.y;
        *(float2*)(g_xr + (size_t)s * CDIM + n) = v;
    } else if (MODE == 2) {
        *(u32*)(g_hb + (size_t)r * HIDD + n) = bfpack(gelu_exact(v.x), gelu_exact(v.y));
    } else {
        float2 a = *(const float2*)(g_xr + (size_t)r * CDIM + n);
        v.x += a.x; v.y += a.y;
        *(float2*)(outp + (size_t)r * CDIM + n) = v;
    }
}

// ============ A-resident GEMM for K=192, double-buffered B, 2 CTAs/SM ============
// A tile in smem (loaded once); a-frags re-ldmatrix'd per k-step (keeps regs <=124
// so TWO CTAs fit per SM -> sync/epilogue stalls of one CTA overlap the other's MMAs).
#define ARES_SMEM (128 * 400 + 2 * 64 * 400)
template <int MODE>
__global__ __launch_bounds__(256, 2) void tmmaA(const float* __restrict__ bias,
                                                const float* __restrict__ aux,
                                                float* __restrict__ outp, int NT) {
    extern __shared__ __align__(16) char sm[];
    char* As = sm;                       // 128 * 400
    char* Bs = sm + 128 * 400;           // 2 buffers * 64 * 400

    const __nv_bfloat16* Ag = (MODE == 1) ? g_aob : g_xwb;
    const __nv_bfloat16* Wt = (MODE == 0) ? g_wqkv : (MODE == 1) ? g_wproj : g_wfc1;

    int tid = threadIdx.x;
    int w = tid >> 5, l = tid & 31;
    int wm = w & 3, wn = w >> 2;
    int m0 = blockIdx.x * 128;

    // prefetch B tile 0
    uint4 pf[6];
#pragma unroll
    for (int j = 0; j < 6; j++) {
        int id = tid + j * 256;
        int row = id / 24, ch = id - row * 24;
        pf[j] = *(const uint4*)(Wt + (size_t)row * 192 + ch * 8);
    }
    // load A tile
#pragma unroll
    for (int j = 0; j < 12; j++) {
        int id = tid + j * 256;
        int row = id / 24, ch = id - row * 24;
        *(uint4*)(As + row * 400 + ch * 16) =
            *(const uint4*)(Ag + (size_t)(m0 + row) * 192 + ch * 8);
    }
    // store B tile 0 into buffer 0
#pragma unroll
    for (int j = 0; j < 6; j++) {
        int id = tid + j * 256;
        int row = id / 24, ch = id - row * 24;
        *(uint4*)(Bs + row * 400 + ch * 16) = pf[j];
    }
    __syncthreads();

    u32 sa = smem_u32(As), sb0 = smem_u32(Bs);
    u32 aBase0 = sa + (wm * 32 + (l & 15)) * 400 + (l >> 4) * 16;        // mt=0
    u32 aBase1 = aBase0 + 16 * 400;                                      // mt=1

    // prefetch tile 1
    if (NT > 1) {
        const __nv_bfloat16* Wn = Wt + (size_t)64 * 192;
#pragma unroll
        for (int j = 0; j < 6; j++) {
            int id = tid + j * 256;
            int row = id / 24, ch = id - row * 24;
            pf[j] = *(const uint4*)(Wn + (size_t)row * 192 + ch * 8);
        }
    }

    u32 bOff = (wn * 32 + (l & 7) + ((l >> 3) & 1) * 8) * 400 + (l >> 4) * 16;
    int lq = l >> 2, lr = l & 3;

    for (int nt = 0; nt < NT; nt++) {
        int cur = nt & 1;
        // 1. store prefetched tile nt+1 into alt buffer
        if (nt + 1 < NT) {
            char* Bn = Bs + (1 - cur) * 25600;
#pragma unroll
            for (int j = 0; j < 6; j++) {
                int id = tid + j * 256;
                int row = id / 24, ch = id - row * 24;
                *(uint4*)(Bn + row * 400 + ch * 16) = pf[j];
            }
        }
        // 2. prefetch tile nt+2
        if (nt + 2 < NT) {
            const __nv_bfloat16* Wn = Wt + (size_t)(nt + 2) * 64 * 192;
#pragma unroll
            for (int j = 0; j < 6; j++) {
                int id = tid + j * 256;
                int row = id / 24, ch = id - row * 24;
                pf[j] = *(const uint4*)(Wn + (size_t)row * 192 + ch * 8);
            }
        }
        // 3. MMAs on current buffer (a-frags reloaded per k-step; regs stay low)
        u32 bBase = sb0 + cur * 25600 + bOff;
        float d[2][4][4];
#pragma unroll
        for (int mt = 0; mt < 2; mt++)
#pragma unroll
            for (int nj = 0; nj < 4; nj++)
#pragma unroll
                for (int q = 0; q < 4; q++) d[mt][nj][q] = 0.0f;

#pragma unroll
        for (int ks = 0; ks < 12; ks++) {
            u32 a0[4], a1[4], r0[4], r1[4];
            LDM4(a0, aBase0 + ks * 32);
            LDM4(a1, aBase1 + ks * 32);
            LDM4(r0, bBase + ks * 32);
            LDM4(r1, bBase + 6400 + ks * 32);
            MMA(d[0][0], a0, r0[0], r0[2]);
            MMA(d[0][1], a0, r0[1], r0[3]);
            MMA(d[0][2], a0, r1[0], r1[2]);
            MMA(d[0][3], a0, r1[1], r1[3]);
            MMA(d[1][0], a1, r0[0], r0[2]);
            MMA(d[1][1], a1, r0[1], r0[3]);
            MMA(d[1][2], a1, r1[0], r1[2]);
            MMA(d[1][3], a1, r1[1], r1[3]);
        }
        // 4. epilogue
#pragma unroll
        for (int mt = 0; mt < 2; mt++) {
            int ra = m0 + wm * 32 + mt * 16 + lq;
            int rb = ra + 8;
#pragma unroll
            for (int nj = 0; nj < 4; nj++) {
                int ng = nt * 64 + wn * 32 + nj * 8 + lr * 2;
                float2 b2 = *(const float2*)(bias + ng);
                float2 v0 = make_float2(d[mt][nj][0] + b2.x, d[mt][nj][1] + b2.y);
                float2 v1 = make_float2(d[mt][nj][2] + b2.x, d[mt][nj][3] + b2.y);
                store2<MODE>(ra, ng, v0, aux, outp);
                store2<MODE>(rb, ng, v1, aux, outp);
            }
        }
        __syncthreads();
    }
}

// ============ fc2 GEMM: K=768, BM=128, BN=192 single pass, double-buffered ============
// layout: A0@0 (10240), B0@10240 (15360), A1@25600, B1@35840 ; total 51200
#define FC2_SMEM (2 * (128 * 80 + 192 * 80))
__global__ __launch_bounds__(256) void tmmaF(const float* __restrict__ bias,
                                             float* __restrict__ outp) {
    extern __shared__ __align__(16) char smF[];
    int tid = threadIdx.x;
    int w = tid >> 5, l = tid & 31;
    int wm = w & 3, wn = w >> 2;   // 4 x 2 warps; warp tile 32 x 96
    int m0 = blockIdx.x * 128;

    const __nv_bfloat16* Ag = g_hb;
    const __nv_bfloat16* Wt = g_wfc2;

    u32 s0 = smem_u32(smF);
    u32 aOff = (wm * 32 + (l & 7) + ((l >> 3) & 1) * 8) * 80 + (l >> 4) * 16;
    u32 bOff = 10240 + (wn * 96 + (l & 7) + ((l >> 3) & 1) * 8) * 80 + (l >> 4) * 16;

    float d[2][12][4];
#pragma unroll
    for (int mt = 0; mt < 2; mt++)
#pragma unroll
        for (int nj = 0; nj < 12; nj++)
#pragma unroll
            for (int q = 0; q < 4; q++) d[mt][nj][q] = 0.0f;

    uint4 pa[2], pb[3];
#pragma unroll
    for (int j = 0; j < 2; j++) {
        int id = tid + j * 256;
        pa[j] = *(const uint4*)(Ag + (size_t)(m0 + (id >> 2)) * HIDD + (id & 3) * 8);
    }
#pragma unroll
    for (int j = 0; j < 3; j++) {
        int id = tid + j * 256;
        pb[j] = *(const uint4*)(Wt + (size_t)(id >> 2) * HIDD + (id & 3) * 8);
    }
    // store k-slab 0 into buffer 0
#pragma unroll
    for (int j = 0; j < 2; j++) {
        int id = tid + j * 256;
        *(uint4*)(smF + (id >> 2) * 80 + (id & 3) * 16) = pa[j];
    }
#pragma unroll
    for (int j = 0; j < 3; j++) {
        int id = tid + j * 256;
        *(uint4*)(smF + 10240 + (id >> 2) * 80 + (id & 3) * 16) = pb[j];
    }
    __syncthreads();
    // prefetch slab 1
    {
#pragma unroll
        for (int j = 0; j < 2; j++) {
            int id = tid + j * 256;
            pa[j] = *(const uint4*)(Ag + (size_t)(m0 + (id >> 2)) * HIDD + 32 + (id & 3) * 8);
        }
#pragma unroll
        for (int j = 0; j < 3; j++) {
            int id = tid + j * 256;
            pb[j] = *(const uint4*)(Wt + (size_t)(id >> 2) * HIDD + 32 + (id & 3) * 8);
        }
    }

    for (int kt = 0; kt < 24; kt++) {
        int cur = kt & 1;
        // 1. store prefetched slab kt+1 into alt buffer
        if (kt + 1 < 24) {
            char* base = smF + (1 - cur) * 25600;
#pragma unroll
            for (int j = 0; j < 2; j++) {
                int id = tid + j * 256;
                *(uint4*)(base + (id >> 2) * 80 + (id & 3) * 16) = pa[j];
            }
#pragma unroll
            for (int j = 0; j < 3; j++) {
                int id = tid + j * 256;
                *(uint4*)(base + 10240 + (id >> 2) * 80 + (id & 3) * 16) = pb[j];
            }
        }
        // 2. prefetch slab kt+2
        if (kt + 2 < 24) {
            int kc = (kt + 2) * 32;
#pragma unroll
            for (int j = 0; j < 2; j++) {
                int id = tid + j * 256;
                pa[j] = *(const uint4*)(Ag + (size_t)(m0 + (id >> 2)) * HIDD + kc + (id & 3) * 8);
            }
#pragma unroll
            for (int j = 0; j < 3; j++) {
                int id = tid + j * 256;
                pb[j] = *(const uint4*)(Wt + (size_t)(id >> 2) * HIDD + kc + (id & 3) * 8);
            }
        }
        // 3. MMAs on current buffer
        u32 aBase = s0 + cur * 25600 + aOff;
        u32 bBase = s0 + cur * 25600 + bOff;
#pragma unroll
        for (int ks = 0; ks < 2; ks++) {
            u32 a0[4], a1[4];
            LDM4(a0, aBase + ks * 32);
            LDM4(a1, aBase + 1280 + ks * 32);
#pragma unroll
            for (int g = 0; g < 6; g++) {
                u32 rg[4];
                LDM4(rg, bBase + g * 1280 + ks * 32);
                MMA(d[0][2 * g],     a0, rg[0], rg[2]);
                MMA(d[0][2 * g + 1], a0, rg[1], rg[3]);
                MMA(d[1][2 * g],     a1, rg[0], rg[2]);
                MMA(d[1][2 * g + 1], a1, rg[1], rg[3]);
            }
        }
        __syncthreads();
    }

    int lq = l >> 2, lr = l & 3;
#pragma unroll
    for (int mt = 0; mt < 2; mt++) {
        int ra = m0 + wm * 32 + mt * 16 + lq;
        int rb = ra + 8;
#pragma unroll
        for (int nj = 0; nj < 12; nj++) {
            int ng = wn * 96 + nj * 8 + lr * 2;
            float2 b2 = *(const float2*)(bias + ng);
            float2 v0 = make_float2(d[mt][nj][0] + b2.x, d[mt][nj][1] + b2.y);
            float2 v1 = make_float2(d[mt][nj][2] + b2.x, d[mt][nj][3] + b2.y);
            store2<3>(ra, ng, v0, nullptr, outp);
            store2<3>(rb, ng, v1, nullptr, outp);
        }
    }
}

// ============ tensor-core attention: one block per (window, head) ============
// 8 warps, two 128-query passes; keys split into two 128-halves to cut registers
// (sum + unnormalized O accumulate across halves — identical math, no rescale).
#define ATT_SMEM (256 * 80 * 3)
__global__ __launch_bounds__(256, 2) void attn_mma(const float* __restrict__ mask) {
    extern __shared__ __align__(16) char sm[];
    char* Qs = sm;
    char* Ksm = sm + 256 * 80;
    char* Vsm = sm + 2 * 256 * 80;

    int bid = blockIdx.x;
    int wnd = bid / 6;
    int head = bid - wnd * 6;
    int tid = threadIdx.x;

    size_t gbase = (size_t)((wnd * 6 + head) * 256) * 32;
    const uint4* Qg = (const uint4*)(g_q + gbase);
    const uint4* Kg = (const uint4*)(g_k + gbase);
    const uint4* Vg = (const uint4*)(g_v + gbase);
    for (int i = tid; i < 1024; i += 256) {
        int row = i >> 2, c4 = i & 3;
        int off = row * 80 + c4 * 16;
        *(uint4*)(Qs + off)  = Qg[i];
        *(uint4*)(Ksm + off) = Kg[i];
        *(uint4*)(Vsm + off) = Vg[i];
    }
    __syncthreads();

    int w = tid >> 5, l = tid & 31;
    u32 sQ = smem_u32(Qs), sK = smem_u32(Ksm), sV = smem_u32(Vsm);
    bool border = ((wnd >> 4) == 15) || ((wnd & 15) == 15);

#pragma unroll 1
    for (int hh = 0; hh < 2; hh++) {
        int qr = hh * 128 + w * 16;
        u32 qa[8];
        LDM4(qa,     sQ + (qr + (l & 15)) * 80 + (l >> 4) * 16);
        LDM4(qa + 4, sQ + (qr + (l & 15)) * 80 + 32 + (l >> 4) * 16);

        int r0 = qr + (l >> 2);
        const __nv_bfloat16* bA = g_bias6b + head * 65536 + r0 * 256;
        const __nv_bfloat16* bB = bA + 2048;
        const float* mA = mask + (size_t)wnd * 65536 + r0 * 256;
        const float* mB = mA + 2048;

        float sA = 0.0f, sB = 0.0f;
        float o[4][4];
#pragma unroll
        for (int nt = 0; nt < 4; nt++)
#pragma unroll
            for (int q = 0; q < 4; q++) o[nt][q] = 0.0f;

#pragma unroll 1
        for (int kh = 0; kh < 2; kh++) {
            int kb0 = kh * 128;
            float d[16][4];
#pragma unroll
            for (int t = 0; t < 16; t++)
#pragma unroll
                for (int q = 0; q < 4; q++) d[t][q] = 0.0f;

#pragma unroll
            for (int t = 0; t < 16; t++) {
                u32 kb[4];
                LDM4(kb, sK + (kb0 + t * 8 + (l & 7)) * 80 + (l >> 3) * 16);
                MMA(d[t], qa, kb[0], kb[1]);
                MMA(d[t], qa + 4, kb[2], kb[3]);
            }

            u32 pbf[8][4];
#pragma unroll
            for (int t = 0; t < 16; t++) {
                int c = kb0 + t * 8 + 2 * (l & 3);
                float2 aA = __bfloat1622float2(*(const __nv_bfloat162*)(bA + c));
                float2 aB = __bfloat1622float2(*(const __nv_bfloat162*)(bB + c));
                if (border) {
                    float2 ma = *(const float2*)(mA + c);
                    float2 mb = *(const float2*)(mB + c);
                    aA.x += ma.x; aA.y += ma.y;
                    aB.x += mb.x; aB.y += mb.y;
                }
                float p0 = __expf(d[t][0] + aA.x);
                float p1 = __expf(d[t][1] + aA.y);
                float p2 = __expf(d[t][2] + aB.x);
                float p3 = __expf(d[t][3] + aB.y);
                sA += p0 + p1;
                sB += p2 + p3;
                int kt = t >> 1, s4 = (t & 1) * 2;
                pbf[kt][s4]     = bfpack(p0, p1);
                pbf[kt][s4 + 1] = bfpack(p2, p3);
            }

#pragma unroll
            for (int kt = 0; kt < 8; kt++) {
                u32 v0[4], v1[4];
                u32 vaddr = sV + (kb0 + kt * 16 + (l & 7) + ((l >> 3) & 1) * 8) * 80 + (l >> 4) * 16;
                LDM4T(v0, vaddr);
                LDM4T(v1, vaddr + 32);
                MMA(o[0], pbf[kt], v0[0], v0[1]);
                MMA(o[1], pbf[kt], v0[2], v0[3]);
                MMA(o[2], pbf[kt], v1[0], v1[1]);
                MMA(o[3], pbf[kt], v1[2], v1[3]);
            }
        }

        sA += __shfl_xor_sync(0xffffffffu, sA, 1);
        sA += __shfl_xor_sync(0xffffffffu, sA, 2);
        sB += __shfl_xor_sync(0xffffffffu, sB, 1);
        sB += __shfl_xor_sync(0xffffffffu, sB, 2);
        float invA = 1.0f / sA, invB = 1.0f / sB;

        __nv_bfloat16* OA = g_aob + (size_t)(wnd * 256 + r0) * CDIM + head * 32;
        __nv_bfloat16* OB = OA + (size_t)8 * CDIM;
#pragma unroll
        for (int nt = 0; nt < 4; nt++) {
            int c = nt * 8 + 2 * (l & 3);
            *(u32*)(OA + c) = bfpack(o[nt][0] * invA, o[nt][1] * invA);
            *(u32*)(OB + c) = bfpack(o[nt][2] * invB, o[nt][3] * invB);
        }
    }
}

// ============ host launcher ============
extern "C" void kernel_launch(void* const* d_in, const int* in_sizes, int n_in,
                              void* d_out, int out_size) {
    const float* x     = (const float*)d_in[0];
    const int*   rpi   = (const int*)d_in[1];
    const float* mask  = (const float*)d_in[2];
    const float* n1g   = (const float*)d_in[3];
    const float* n1b   = (const float*)d_in[4];
    const float* qkvw  = (const float*)d_in[5];
    const float* qkvb  = (const float*)d_in[6];
    const float* rpb   = (const float*)d_in[7];
    const float* projw = (const float*)d_in[8];
    const float* projb = (const float*)d_in[9];
    const float* n2g   = (const float*)d_in[10];
    const float* n2b   = (const float*)d_in[11];
    const float* fc1w  = (const float*)d_in[12];
    const float* fc1b  = (const float*)d_in[13];
    const float* fc2w  = (const float*)d_in[14];
    const float* fc2b  = (const float*)d_in[15];
    float* out = (float*)d_out;

    cudaFuncSetAttribute(attn_mma, cudaFuncAttributeMaxDynamicSharedMemorySize, ATT_SMEM);
    cudaFuncSetAttribute(tmmaA<0>, cudaFuncAttributeMaxDynamicSharedMemorySize, ARES_SMEM);
    cudaFuncSetAttribute(tmmaA<1>, cudaFuncAttributeMaxDynamicSharedMemorySize, ARES_SMEM);
    cudaFuncSetAttribute(tmmaA<2>, cudaFuncAttributeMaxDynamicSharedMemorySize, ARES_SMEM);
    cudaFuncSetAttribute(tmmaF, cudaFuncAttributeMaxDynamicSharedMemorySize, FC2_SMEM);

    transw_all<<<1728, 256>>>(qkvw, projw, fc1w, fc2w);
    bias6_kernel<<<1536, 256>>>(rpi, rpb);

    ln_kernel<<<512, 256>>>(x, n1g, n1b, 1);                            // LN1 + shift + partition
    tmmaA<0><<<512, 256, ARES_SMEM>>>(qkvb, nullptr, nullptr, 9);       // QKV -> q/k/v bf16
    attn_mma<<<1536, 256, ATT_SMEM>>>(mask);                            // attention -> g_aob
    tmmaA<1><<<512, 256, ARES_SMEM>>>(projb, x, nullptr, 3);            // proj + reverse + resid
    ln_kernel<<<512, 256>>>(x, n2g, n2b, 0);                            // LN2 (reads g_xr)
    tmmaA<2><<<512, 256, ARES_SMEM>>>(fc1b, nullptr, nullptr, 12);      // fc1 + GELU -> g_hb
    tmmaF<<<512, 256, FC2_SMEM>>>(fc2b, out);                           // fc2 + resid -> out
}